// round 1
// baseline (speedup 1.0000x reference)
#include <cuda_runtime.h>
#include <cuda_bf16.h>
#include <math.h>

// Problem constants
#define Bx 4
#define Sx 1024
#define Dx 1024
#define Hx 16
#define HDx 64
#define TDx 3072   // 3*D
#define QT 8       // q rows per attention CTA

// Scratch (no cudaMalloc allowed)
__device__ float g_qkv[Bx * Sx * TDx];    // [B*S, 3D]
__device__ float g_aout[Bx * Sx * Dx];    // merged-head attention output [B*S, D]

// ---------------------------------------------------------------------------
// Generic tiled GEMM: C[M,N] = A[M,K] @ B[K,N] + bias[N]
// 64x64 block tile, 16x16 threads, 4x4 per thread, K-tile 16
// ---------------------------------------------------------------------------
__global__ void gemm_bias_kernel(const float* __restrict__ A,
                                 const float* __restrict__ B,
                                 const float* __restrict__ bias,
                                 float* __restrict__ C,
                                 int M, int N, int K) {
    const int BM = 64, BN = 64, BK = 16;
    __shared__ __align__(16) float As[BK][BM + 1];  // +1 pad: stride 65 ≡ 1 mod 32
    __shared__ __align__(16) float Bs[BK][BN];

    int t  = threadIdx.x;
    int tx = t & 15;        // 0..15  (N direction)
    int ty = t >> 4;        // 0..15  (M direction)
    int row0 = blockIdx.y * BM;
    int col0 = blockIdx.x * BN;

    float acc[4][4] = {};

    for (int k0 = 0; k0 < K; k0 += BK) {
        // Load A tile (BM x BK), transposed into As[k][m]
        #pragma unroll
        for (int i = 0; i < 4; i++) {
            int r = (t >> 4) + 16 * i;   // 0..63
            int c = t & 15;              // 0..15
            As[c][r] = A[(size_t)(row0 + r) * K + k0 + c];
        }
        // Load B tile (BK x BN)
        #pragma unroll
        for (int i = 0; i < 4; i++) {
            int c = (t >> 6) + 4 * i;    // 0..15
            int n = t & 63;              // 0..63
            Bs[c][n] = B[(size_t)(k0 + c) * N + col0 + n];
        }
        __syncthreads();

        #pragma unroll
        for (int kk = 0; kk < BK; kk++) {
            float a[4], b[4];
            #pragma unroll
            for (int m = 0; m < 4; m++) a[m] = As[kk][ty * 4 + m];
            #pragma unroll
            for (int n = 0; n < 4; n++) b[n] = Bs[kk][tx * 4 + n];
            #pragma unroll
            for (int m = 0; m < 4; m++)
                #pragma unroll
                for (int n = 0; n < 4; n++)
                    acc[m][n] += a[m] * b[n];
        }
        __syncthreads();
    }

    #pragma unroll
    for (int m = 0; m < 4; m++) {
        int r = row0 + ty * 4 + m;
        #pragma unroll
        for (int n = 0; n < 4; n++) {
            int c = col0 + tx * 4 + n;
            C[(size_t)r * N + c] = acc[m][n] + bias[c];
        }
    }
}

// ---------------------------------------------------------------------------
// Attention kernel: per (b, h, 8-q-row tile)
//   scores = Q K^T / 8  (+mask, causal)  -> softmax -> write w -> PV -> aout
// ---------------------------------------------------------------------------
__global__ void attn_kernel(const float* __restrict__ qkv,
                            const float* __restrict__ mask,
                            float* __restrict__ w_out,
                            float* __restrict__ aout) {
    const int q0 = blockIdx.x * QT;
    const int h  = blockIdx.y;
    const int b  = blockIdx.z;
    const int t  = threadIdx.x;   // 256 threads

    __shared__ __align__(16) float qs[QT][HDx];        // 2 KB
    __shared__ __align__(16) float probs[QT][Sx];      // 32 KB
    __shared__ __align__(16) float part[4][QT][HDx];   // 8 KB

    const float* base = qkv + (size_t)b * Sx * TDx;

    // Load Q tile: QT*64 = 512 floats, 2 per thread
    #pragma unroll
    for (int i = 0; i < 2; i++) {
        int idx = t + i * 256;
        int r = idx >> 6, d = idx & 63;
        qs[r][d] = base[(size_t)(q0 + r) * TDx + h * HDx + d];
    }
    __syncthreads();

    // ---- Phase 1: raw scores ----
    const int jtop = q0 + QT - 1;   // largest valid j in this tile
    #pragma unroll
    for (int i = 0; i < 4; i++) {
        int j = t + i * 256;
        float mk = mask[b * Sx + j];
        if (j <= jtop) {
            const float4* kp = (const float4*)(base + (size_t)j * TDx + Dx + h * HDx);
            float acc[QT];
            #pragma unroll
            for (int r = 0; r < QT; r++) acc[r] = 0.f;
            #pragma unroll
            for (int d4 = 0; d4 < 16; d4++) {
                float4 kv = kp[d4];
                #pragma unroll
                for (int r = 0; r < QT; r++) {
                    float4 qv = ((const float4*)qs[r])[d4];
                    acc[r] += qv.x * kv.x + qv.y * kv.y + qv.z * kv.z + qv.w * kv.w;
                }
            }
            #pragma unroll
            for (int r = 0; r < QT; r++)
                probs[r][j] = (j <= q0 + r) ? acc[r] * 0.125f + mk : -10000.f + mk;
        } else {
            #pragma unroll
            for (int r = 0; r < QT; r++)
                probs[r][j] = -10000.f + mk;
        }
    }
    __syncthreads();

    // ---- Phase 2: softmax per row (warp r handles row r), write w ----
    {
        int warp = t >> 5, lane = t & 31;   // 8 warps == QT rows
        float mx = -1e30f;
        #pragma unroll
        for (int k = 0; k < 32; k++) mx = fmaxf(mx, probs[warp][lane + 32 * k]);
        #pragma unroll
        for (int o = 16; o > 0; o >>= 1) mx = fmaxf(mx, __shfl_xor_sync(0xffffffffu, mx, o));

        float sum = 0.f;
        #pragma unroll
        for (int k = 0; k < 32; k++) {
            float p = expf(probs[warp][lane + 32 * k] - mx);
            probs[warp][lane + 32 * k] = p;
            sum += p;
        }
        #pragma unroll
        for (int o = 16; o > 0; o >>= 1) sum += __shfl_xor_sync(0xffffffffu, sum, o);
        float inv = 1.f / sum;

        size_t wbase = ((size_t)((b * Hx + h) * Sx + (q0 + warp))) * Sx;
        #pragma unroll
        for (int k = 0; k < 32; k++) {
            int j = lane + 32 * k;
            float p = probs[warp][j] * inv;
            probs[warp][j] = p;
            w_out[wbase + j] = p;
        }
    }
    __syncthreads();

    // ---- Phase 3: PV  (4 j-groups x 64 head-dims) ----
    {
        int g = t >> 6, d = t & 63;
        float acc[QT];
        #pragma unroll
        for (int r = 0; r < QT; r++) acc[r] = 0.f;
        for (int j = g; j <= jtop; j += 4) {
            float v = base[(size_t)j * TDx + 2 * Dx + h * HDx + d];
            #pragma unroll
            for (int r = 0; r < QT; r++) acc[r] += probs[r][j] * v;
        }
        #pragma unroll
        for (int r = 0; r < QT; r++) part[g][r][d] = acc[r];
    }
    __syncthreads();

    // combine partials, write merged-head layout aout[b*S+q][h*64+d]
    #pragma unroll
    for (int i = 0; i < 2; i++) {
        int idx = t + i * 256;
        int r = idx >> 6, d = idx & 63;
        float s = part[0][r][d] + part[1][r][d] + part[2][r][d] + part[3][r][d];
        aout[((size_t)(b * Sx + q0 + r)) * Dx + h * HDx + d] = s;
    }
}

// ---------------------------------------------------------------------------
extern "C" void kernel_launch(void* const* d_in, const int* in_sizes, int n_in,
                              void* d_out, int out_size) {
    const float* x      = (const float*)d_in[0];  // [B,S,D]
    const float* mask   = (const float*)d_in[1];  // [B,1,1,S]
    const float* w_attn = (const float*)d_in[2];  // [D,3D]
    const float* b_attn = (const float*)d_in[3];  // [1,3D]
    const float* w_proj = (const float*)d_in[4];  // [D,D]
    const float* b_proj = (const float*)d_in[5];  // [1,D]

    float* out_a = (float*)d_out;                              // [B,S,D]
    float* out_w = (float*)d_out + (size_t)Bx * Sx * Dx;       // [B,H,S,S]

    float* qkv;  cudaGetSymbolAddress((void**)&qkv,  g_qkv);
    float* aout; cudaGetSymbolAddress((void**)&aout, g_aout);

    // K1: qkv = x @ w_attn + b_attn   (4096 x 3072 x 1024)
    {
        dim3 grid(TDx / 64, (Bx * Sx) / 64);
        gemm_bias_kernel<<<grid, 256>>>(x, w_attn, b_attn, qkv,
                                        Bx * Sx, TDx, Dx);
    }
    // K2: attention (scores+softmax+w store+PV)
    {
        dim3 grid(Sx / QT, Hx, Bx);
        attn_kernel<<<grid, 256>>>(qkv, mask, out_w, aout);
    }
    // K3: a = aout @ w_proj + b_proj  (4096 x 1024 x 1024)
    {
        dim3 grid(Dx / 64, (Bx * Sx) / 64);
        gemm_bias_kernel<<<grid, 256>>>(aout, w_proj, b_proj, out_a,
                                        Bx * Sx, Dx, Dx);
    }
}

// round 2
// speedup vs baseline: 1.2540x; 1.2540x over previous
#include <cuda_runtime.h>
#include <cuda_bf16.h>
#include <math.h>

// Problem constants
#define Bx 4
#define Sx 1024
#define Dx 1024
#define Hx 16
#define HDx 64
#define TDx 3072   // 3*D
#define QT 8       // q rows per attention CTA

// Scratch (no cudaMalloc allowed)
__device__ float g_qkv[Bx * Sx * TDx];    // [B*S, 3D]
__device__ float g_aout[Bx * Sx * Dx];    // merged-head attention output [B*S, D]

// ---------------------------------------------------------------------------
// tf32 helpers
// ---------------------------------------------------------------------------
__device__ __forceinline__ unsigned f2tf32(float f) {
    unsigned r;
    asm("cvt.rna.tf32.f32 %0, %1;" : "=r"(r) : "f"(f));
    return r;
}

__device__ __forceinline__ void mma_tf32(float c[4], const unsigned a[4], const unsigned b[2]) {
    asm volatile("mma.sync.aligned.m16n8k8.row.col.f32.tf32.tf32.f32 "
        "{%0,%1,%2,%3}, {%4,%5,%6,%7}, {%8,%9}, {%0,%1,%2,%3};"
        : "+f"(c[0]), "+f"(c[1]), "+f"(c[2]), "+f"(c[3])
        : "r"(a[0]), "r"(a[1]), "r"(a[2]), "r"(a[3]), "r"(b[0]), "r"(b[1]));
}

// ---------------------------------------------------------------------------
// tf32 tensor-core GEMM: C[M,N] = A[M,K] @ B[K,N] + bias[N]
// Block tile 128x128, K-tile 16. 256 threads = 8 warps (2 in M x 4 in N),
// warp tile 64x32. SMEM staged in mma fragment layout:
//   A frag load = 1x LDS.128 / (m-tile,k-step), B frag = 1x LDS.64.
// Double buffered.
// ---------------------------------------------------------------------------
__global__ __launch_bounds__(256) void gemm_mma(const float* __restrict__ A,
                                                const float* __restrict__ B,
                                                const float* __restrict__ bias,
                                                float* __restrict__ C,
                                                int M, int N, int K) {
    __shared__ unsigned Afrag[2][2][8][32][4];   // [buf][ks][mi][lane][reg] 16KB
    __shared__ unsigned Bfrag[2][2][16][32][2];  // [buf][ks][ni][lane][reg] 16KB

    const int t = threadIdx.x;
    const int warp = t >> 5, lane = t & 31;
    const int wm = warp >> 2;       // 0..1
    const int wn = warp & 3;        // 0..3
    const int row0 = blockIdx.y * 128, col0 = blockIdx.x * 128;

    float c[4][4][4];
    #pragma unroll
    for (int i = 0; i < 4; i++)
        #pragma unroll
        for (int j = 0; j < 4; j++)
            #pragma unroll
            for (int r = 0; r < 4; r++) c[i][j][r] = 0.f;

    float4 aReg[2], bReg[2];

    // global tile load: A 128x16 (2 float4/thread), B 16x128 (2 float4/thread)
    auto loadG = [&](int k0) {
        #pragma unroll
        for (int i = 0; i < 2; i++) {
            int idx = t * 2 + i;
            int m = idx >> 2, kq = idx & 3;
            aReg[i] = *(const float4*)&A[(size_t)(row0 + m) * K + k0 + kq * 4];
            int kr = idx >> 5, nq = idx & 31;
            bReg[i] = *(const float4*)&B[(size_t)(k0 + kr) * N + col0 + nq * 4];
        }
    };
    // scatter into fragment layout (+ tf32 convert)
    auto stageS = [&](int buf) {
        #pragma unroll
        for (int i = 0; i < 2; i++) {
            int idx = t * 2 + i;
            int m = idx >> 2, kq = idx & 3;
            const float* av = (const float*)&aReg[i];
            #pragma unroll
            for (int e = 0; e < 4; e++) {
                int kl = kq * 4 + e;
                int ks = kl >> 3, cc = kl & 7;
                int mi = m >> 4, r = m & 15;
                int tt = (r & 7) * 4 + (cc & 3);
                int reg = (r >> 3) + ((cc >> 2) << 1);
                Afrag[buf][ks][mi][tt][reg] = f2tf32(av[e]);
            }
            int kr = idx >> 5, nq = idx & 31;
            const float* bv = (const float*)&bReg[i];
            #pragma unroll
            for (int e = 0; e < 4; e++) {
                int nl = nq * 4 + e;
                int ks = kr >> 3, kc = kr & 7;
                int ni = nl >> 3, nr = nl & 7;
                int tt = nr * 4 + (kc & 3);
                int reg = kc >> 2;
                Bfrag[buf][ks][ni][tt][reg] = f2tf32(bv[e]);
            }
        }
    };

    loadG(0);
    stageS(0);
    __syncthreads();

    const int NT = K / 16;
    for (int kt = 0; kt < NT; kt++) {
        int buf = kt & 1;
        if (kt + 1 < NT) loadG((kt + 1) * 16);
        #pragma unroll
        for (int ks = 0; ks < 2; ks++) {
            unsigned a[4][4];
            unsigned b[4][2];
            #pragma unroll
            for (int mm = 0; mm < 4; mm++) {
                uint4 v = *(const uint4*)&Afrag[buf][ks][wm * 4 + mm][lane][0];
                a[mm][0] = v.x; a[mm][1] = v.y; a[mm][2] = v.z; a[mm][3] = v.w;
            }
            #pragma unroll
            for (int nn = 0; nn < 4; nn++) {
                uint2 v = *(const uint2*)&Bfrag[buf][ks][wn * 4 + nn][lane][0];
                b[nn][0] = v.x; b[nn][1] = v.y;
            }
            #pragma unroll
            for (int mm = 0; mm < 4; mm++)
                #pragma unroll
                for (int nn = 0; nn < 4; nn++)
                    mma_tf32(c[mm][nn], a[mm], b[nn]);
        }
        if (kt + 1 < NT) stageS((kt + 1) & 1);
        __syncthreads();
    }

    // epilogue: c0/c1 at (r, 2c..2c+1), c2/c3 at (r+8, ...)
    #pragma unroll
    for (int mm = 0; mm < 4; mm++) {
        int r0 = row0 + wm * 64 + mm * 16 + (lane >> 2);
        #pragma unroll
        for (int nn = 0; nn < 4; nn++) {
            int cc0 = col0 + wn * 32 + nn * 8 + 2 * (lane & 3);
            float2 bv = *(const float2*)&bias[cc0];
            float2 o0 = {c[mm][nn][0] + bv.x, c[mm][nn][1] + bv.y};
            float2 o1 = {c[mm][nn][2] + bv.x, c[mm][nn][3] + bv.y};
            *(float2*)&C[(size_t)r0 * N + cc0] = o0;
            *(float2*)&C[(size_t)(r0 + 8) * N + cc0] = o1;
        }
    }
}

// ---------------------------------------------------------------------------
// Attention kernel: per (b, h, 8-q-row tile)  (unchanged from R1)
// ---------------------------------------------------------------------------
__global__ void attn_kernel(const float* __restrict__ qkv,
                            const float* __restrict__ mask,
                            float* __restrict__ w_out,
                            float* __restrict__ aout) {
    const int q0 = blockIdx.x * QT;
    const int h  = blockIdx.y;
    const int b  = blockIdx.z;
    const int t  = threadIdx.x;   // 256 threads

    __shared__ __align__(16) float qs[QT][HDx];        // 2 KB
    __shared__ __align__(16) float probs[QT][Sx];      // 32 KB
    __shared__ __align__(16) float part[4][QT][HDx];   // 8 KB

    const float* base = qkv + (size_t)b * Sx * TDx;

    #pragma unroll
    for (int i = 0; i < 2; i++) {
        int idx = t + i * 256;
        int r = idx >> 6, d = idx & 63;
        qs[r][d] = base[(size_t)(q0 + r) * TDx + h * HDx + d];
    }
    __syncthreads();

    const int jtop = q0 + QT - 1;
    #pragma unroll
    for (int i = 0; i < 4; i++) {
        int j = t + i * 256;
        float mk = mask[b * Sx + j];
        if (j <= jtop) {
            const float4* kp = (const float4*)(base + (size_t)j * TDx + Dx + h * HDx);
            float acc[QT];
            #pragma unroll
            for (int r = 0; r < QT; r++) acc[r] = 0.f;
            #pragma unroll
            for (int d4 = 0; d4 < 16; d4++) {
                float4 kv = kp[d4];
                #pragma unroll
                for (int r = 0; r < QT; r++) {
                    float4 qv = ((const float4*)qs[r])[d4];
                    acc[r] += qv.x * kv.x + qv.y * kv.y + qv.z * kv.z + qv.w * kv.w;
                }
            }
            #pragma unroll
            for (int r = 0; r < QT; r++)
                probs[r][j] = (j <= q0 + r) ? acc[r] * 0.125f + mk : -10000.f + mk;
        } else {
            #pragma unroll
            for (int r = 0; r < QT; r++)
                probs[r][j] = -10000.f + mk;
        }
    }
    __syncthreads();

    {
        int warp = t >> 5, lane = t & 31;
        float mx = -1e30f;
        #pragma unroll
        for (int k = 0; k < 32; k++) mx = fmaxf(mx, probs[warp][lane + 32 * k]);
        #pragma unroll
        for (int o = 16; o > 0; o >>= 1) mx = fmaxf(mx, __shfl_xor_sync(0xffffffffu, mx, o));

        float sum = 0.f;
        #pragma unroll
        for (int k = 0; k < 32; k++) {
            float p = expf(probs[warp][lane + 32 * k] - mx);
            probs[warp][lane + 32 * k] = p;
            sum += p;
        }
        #pragma unroll
        for (int o = 16; o > 0; o >>= 1) sum += __shfl_xor_sync(0xffffffffu, sum, o);
        float inv = 1.f / sum;

        size_t wbase = ((size_t)((b * Hx + h) * Sx + (q0 + warp))) * Sx;
        #pragma unroll
        for (int k = 0; k < 32; k++) {
            int j = lane + 32 * k;
            float p = probs[warp][j] * inv;
            probs[warp][j] = p;
            w_out[wbase + j] = p;
        }
    }
    __syncthreads();

    {
        int g = t >> 6, d = t & 63;
        float acc[QT];
        #pragma unroll
        for (int r = 0; r < QT; r++) acc[r] = 0.f;
        for (int j = g; j <= jtop; j += 4) {
            float v = base[(size_t)j * TDx + 2 * Dx + h * HDx + d];
            #pragma unroll
            for (int r = 0; r < QT; r++) acc[r] += probs[r][j] * v;
        }
        #pragma unroll
        for (int r = 0; r < QT; r++) part[g][r][d] = acc[r];
    }
    __syncthreads();

    #pragma unroll
    for (int i = 0; i < 2; i++) {
        int idx = t + i * 256;
        int r = idx >> 6, d = idx & 63;
        float s = part[0][r][d] + part[1][r][d] + part[2][r][d] + part[3][r][d];
        aout[((size_t)(b * Sx + q0 + r)) * Dx + h * HDx + d] = s;
    }
}

// ---------------------------------------------------------------------------
extern "C" void kernel_launch(void* const* d_in, const int* in_sizes, int n_in,
                              void* d_out, int out_size) {
    const float* x      = (const float*)d_in[0];  // [B,S,D]
    const float* mask   = (const float*)d_in[1];  // [B,1,1,S]
    const float* w_attn = (const float*)d_in[2];  // [D,3D]
    const float* b_attn = (const float*)d_in[3];  // [1,3D]
    const float* w_proj = (const float*)d_in[4];  // [D,D]
    const float* b_proj = (const float*)d_in[5];  // [1,D]

    float* out_a = (float*)d_out;                              // [B,S,D]
    float* out_w = (float*)d_out + (size_t)Bx * Sx * Dx;       // [B,H,S,S]

    float* qkv;  cudaGetSymbolAddress((void**)&qkv,  g_qkv);
    float* aout; cudaGetSymbolAddress((void**)&aout, g_aout);

    // K1: qkv = x @ w_attn + b_attn   (4096 x 3072 x 1024) — tf32 mma
    {
        dim3 grid(TDx / 128, (Bx * Sx) / 128);
        gemm_mma<<<grid, 256>>>(x, w_attn, b_attn, qkv, Bx * Sx, TDx, Dx);
    }
    // K2: attention (scores+softmax+w store+PV)
    {
        dim3 grid(Sx / QT, Hx, Bx);
        attn_kernel<<<grid, 256>>>(qkv, mask, out_w, aout);
    }
    // K3: a = aout @ w_proj + b_proj  (4096 x 1024 x 1024) — tf32 mma
    {
        dim3 grid(Dx / 128, (Bx * Sx) / 128);
        gemm_mma<<<grid, 256>>>(aout, w_proj, b_proj, out_a, Bx * Sx, Dx, Dx);
    }
}

// round 3
// speedup vs baseline: 1.6587x; 1.3227x over previous
#include <cuda_runtime.h>
#include <cuda_bf16.h>
#include <math.h>

// Problem constants
#define Bx 4
#define Sx 1024
#define Dx 1024
#define Hx 16
#define HDx 64
#define TDx 3072   // 3*D
#define QT 8       // q rows per attention CTA

// Scratch (no cudaMalloc allowed)
__device__ float g_qkv[Bx * Sx * TDx];    // [B*S, 3D]
__device__ float g_aout[Bx * Sx * Dx];    // merged-head attention output
__device__ float g_xr[Bx * Sx * Dx];      // tf32-rounded x
__device__ float g_war[Dx * TDx];         // tf32-rounded w_attn
__device__ float g_wpr[Dx * Dx];          // tf32-rounded w_proj

// ---------------------------------------------------------------------------
__device__ __forceinline__ unsigned f2tf32(float f) {
    unsigned r;
    asm("cvt.rna.tf32.f32 %0, %1;" : "=r"(r) : "f"(f));
    return r;
}

__device__ __forceinline__ void mma_tf32(float c[4], const unsigned a[4], const unsigned b[2]) {
    asm volatile("mma.sync.aligned.m16n8k8.row.col.f32.tf32.tf32.f32 "
        "{%0,%1,%2,%3}, {%4,%5,%6,%7}, {%8,%9}, {%0,%1,%2,%3};"
        : "+f"(c[0]), "+f"(c[1]), "+f"(c[2]), "+f"(c[3])
        : "r"(a[0]), "r"(a[1]), "r"(a[2]), "r"(a[3]), "r"(b[0]), "r"(b[1]));
}

#define CP16(dst, src) asm volatile("cp.async.cg.shared.global [%0], [%1], 16;" :: "r"(dst), "l"(src))
#define CP_COMMIT()    asm volatile("cp.async.commit_group;")
#define CP_WAIT1()     asm volatile("cp.async.wait_group 1;")
#define CP_WAIT0()     asm volatile("cp.async.wait_group 0;")

// ---------------------------------------------------------------------------
// tf32 round elementwise (inputs pre-rounded so GEMM can cp.async raw bits)
// ---------------------------------------------------------------------------
__global__ void round_tf32(const float* __restrict__ in, float* __restrict__ out, int n4) {
    int i = blockIdx.x * blockDim.x + threadIdx.x;
    if (i < n4) {
        float4 v = ((const float4*)in)[i];
        uint4 o;
        o.x = f2tf32(v.x); o.y = f2tf32(v.y); o.z = f2tf32(v.z); o.w = f2tf32(v.w);
        ((uint4*)out)[i] = o;
    }
}

// ---------------------------------------------------------------------------
// tf32 tensor-core GEMM: C[M,N] = A[M,K] @ B[K,N] + bias[N]
// CTA tile 128x128, k-tile 16, 256 threads = 8 warps (2Mx4N), warp 64x32.
// A smem [m][k] stride 20 words, B smem [k][n] stride 136 words:
// both give conflict-free fragment LDS. cp.async double buffered, no STS.
// Inputs must be tf32 bit patterns (pre-rounded); accumulate f32.
// ---------------------------------------------------------------------------
__global__ __launch_bounds__(256) void gemm_mma(const float* __restrict__ A,
                                                const float* __restrict__ B,
                                                const float* __restrict__ bias,
                                                float* __restrict__ C,
                                                int M, int N, int K) {
    __shared__ float As[2][128][20];   // 20480 B
    __shared__ float Bs[2][16][136];   // 17408 B

    const int t = threadIdx.x;
    const int warp = t >> 5, lane = t & 31;
    const int wm = warp >> 2;          // 0..1
    const int wn = warp & 3;           // 0..3
    const int r = lane >> 2;           // 0..7
    const int cq = lane & 3;           // 0..3
    const int row0 = blockIdx.y * 128, col0 = blockIdx.x * 128;

    float acc[4][4][4];
    #pragma unroll
    for (int i = 0; i < 4; i++)
        #pragma unroll
        for (int j = 0; j < 4; j++)
            #pragma unroll
            for (int k = 0; k < 4; k++) acc[i][j][k] = 0.f;

    // cp.async tile loader: A 128x16 (512 x 16B), B 16x128 (512 x 16B), 2+2 per thread
    const int aM0 = (t * 2) >> 2,  aK0 = (t * 2) & 3;        // chunk ids t*2, t*2+1
    const int aM1 = (t * 2 + 1) >> 2, aK1 = (t * 2 + 1) & 3;
    const int bK0 = (t * 2) >> 5,  bN0 = (t * 2) & 31;
    const int bK1 = (t * 2 + 1) >> 5, bN1 = (t * 2 + 1) & 31;

    auto loadG = [&](int buf, int k0) {
        unsigned da0 = (unsigned)__cvta_generic_to_shared(&As[buf][aM0][aK0 * 4]);
        unsigned da1 = (unsigned)__cvta_generic_to_shared(&As[buf][aM1][aK1 * 4]);
        CP16(da0, &A[(size_t)(row0 + aM0) * K + k0 + aK0 * 4]);
        CP16(da1, &A[(size_t)(row0 + aM1) * K + k0 + aK1 * 4]);
        unsigned db0 = (unsigned)__cvta_generic_to_shared(&Bs[buf][bK0][bN0 * 4]);
        unsigned db1 = (unsigned)__cvta_generic_to_shared(&Bs[buf][bK1][bN1 * 4]);
        CP16(db0, &B[(size_t)(k0 + bK0) * N + col0 + bN0 * 4]);
        CP16(db1, &B[(size_t)(k0 + bK1) * N + col0 + bN1 * 4]);
    };

    loadG(0, 0);
    CP_COMMIT();

    const int NT = K / 16;
    for (int kt = 0; kt < NT; kt++) {
        int buf = kt & 1;
        if (kt + 1 < NT) {
            loadG((kt + 1) & 1, (kt + 1) * 16);
            CP_COMMIT();
            CP_WAIT1();
        } else {
            CP_WAIT0();
        }
        __syncthreads();

        #pragma unroll
        for (int ks = 0; ks < 2; ks++) {
            const int kb = ks * 8;
            unsigned a[4][4], b[4][2];
            #pragma unroll
            for (int mm = 0; mm < 4; mm++) {
                const float* ap0 = &As[buf][wm * 64 + mm * 16 + r][kb + cq];
                const float* ap1 = ap0 + 8 * 20;
                a[mm][0] = __float_as_uint(ap0[0]);
                a[mm][1] = __float_as_uint(ap1[0]);
                a[mm][2] = __float_as_uint(ap0[4]);
                a[mm][3] = __float_as_uint(ap1[4]);
            }
            #pragma unroll
            for (int nn = 0; nn < 4; nn++) {
                const float* bp = &Bs[buf][kb + cq][wn * 32 + nn * 8 + r];
                b[nn][0] = __float_as_uint(bp[0]);
                b[nn][1] = __float_as_uint(bp[4 * 136]);
            }
            #pragma unroll
            for (int mm = 0; mm < 4; mm++)
                #pragma unroll
                for (int nn = 0; nn < 4; nn++)
                    mma_tf32(acc[mm][nn], a[mm], b[nn]);
        }
        __syncthreads();   // all warps done with buf before it's refilled
    }

    // epilogue: c0/c1 at (r0, 2c..2c+1), c2/c3 at (r0+8, ...)
    #pragma unroll
    for (int mm = 0; mm < 4; mm++) {
        int r0 = row0 + wm * 64 + mm * 16 + r;
        #pragma unroll
        for (int nn = 0; nn < 4; nn++) {
            int c0 = col0 + wn * 32 + nn * 8 + 2 * cq;
            float2 bv = *(const float2*)&bias[c0];
            float2 o0 = {acc[mm][nn][0] + bv.x, acc[mm][nn][1] + bv.y};
            float2 o1 = {acc[mm][nn][2] + bv.x, acc[mm][nn][3] + bv.y};
            *(float2*)&C[(size_t)r0 * N + c0] = o0;
            *(float2*)&C[(size_t)(r0 + 8) * N + c0] = o1;
        }
    }
}

// ---------------------------------------------------------------------------
// Attention kernel: per (b, h, 8-q-row tile)  (unchanged)
// ---------------------------------------------------------------------------
__global__ void attn_kernel(const float* __restrict__ qkv,
                            const float* __restrict__ mask,
                            float* __restrict__ w_out,
                            float* __restrict__ aout) {
    const int q0 = blockIdx.x * QT;
    const int h  = blockIdx.y;
    const int b  = blockIdx.z;
    const int t  = threadIdx.x;   // 256 threads

    __shared__ __align__(16) float qs[QT][HDx];
    __shared__ __align__(16) float probs[QT][Sx];
    __shared__ __align__(16) float part[4][QT][HDx];

    const float* base = qkv + (size_t)b * Sx * TDx;

    #pragma unroll
    for (int i = 0; i < 2; i++) {
        int idx = t + i * 256;
        int rr = idx >> 6, d = idx & 63;
        qs[rr][d] = base[(size_t)(q0 + rr) * TDx + h * HDx + d];
    }
    __syncthreads();

    const int jtop = q0 + QT - 1;
    #pragma unroll
    for (int i = 0; i < 4; i++) {
        int j = t + i * 256;
        float mk = mask[b * Sx + j];
        if (j <= jtop) {
            const float4* kp = (const float4*)(base + (size_t)j * TDx + Dx + h * HDx);
            float acc[QT];
            #pragma unroll
            for (int rr = 0; rr < QT; rr++) acc[rr] = 0.f;
            #pragma unroll
            for (int d4 = 0; d4 < 16; d4++) {
                float4 kv = kp[d4];
                #pragma unroll
                for (int rr = 0; rr < QT; rr++) {
                    float4 qv = ((const float4*)qs[rr])[d4];
                    acc[rr] += qv.x * kv.x + qv.y * kv.y + qv.z * kv.z + qv.w * kv.w;
                }
            }
            #pragma unroll
            for (int rr = 0; rr < QT; rr++)
                probs[rr][j] = (j <= q0 + rr) ? acc[rr] * 0.125f + mk : -10000.f + mk;
        } else {
            #pragma unroll
            for (int rr = 0; rr < QT; rr++)
                probs[rr][j] = -10000.f + mk;
        }
    }
    __syncthreads();

    {
        int warp = t >> 5, lane = t & 31;
        float mx = -1e30f;
        #pragma unroll
        for (int k = 0; k < 32; k++) mx = fmaxf(mx, probs[warp][lane + 32 * k]);
        #pragma unroll
        for (int o = 16; o > 0; o >>= 1) mx = fmaxf(mx, __shfl_xor_sync(0xffffffffu, mx, o));

        float sum = 0.f;
        #pragma unroll
        for (int k = 0; k < 32; k++) {
            float p = expf(probs[warp][lane + 32 * k] - mx);
            probs[warp][lane + 32 * k] = p;
            sum += p;
        }
        #pragma unroll
        for (int o = 16; o > 0; o >>= 1) sum += __shfl_xor_sync(0xffffffffu, sum, o);
        float inv = 1.f / sum;

        size_t wbase = ((size_t)((b * Hx + h) * Sx + (q0 + warp))) * Sx;
        #pragma unroll
        for (int k = 0; k < 32; k++) {
            int j = lane + 32 * k;
            float p = probs[warp][j] * inv;
            probs[warp][j] = p;
            w_out[wbase + j] = p;
        }
    }
    __syncthreads();

    {
        int g = t >> 6, d = t & 63;
        float acc[QT];
        #pragma unroll
        for (int rr = 0; rr < QT; rr++) acc[rr] = 0.f;
        for (int j = g; j <= jtop; j += 4) {
            float v = base[(size_t)j * TDx + 2 * Dx + h * HDx + d];
            #pragma unroll
            for (int rr = 0; rr < QT; rr++) acc[rr] += probs[rr][j] * v;
        }
        #pragma unroll
        for (int rr = 0; rr < QT; rr++) part[g][rr][d] = acc[rr];
    }
    __syncthreads();

    #pragma unroll
    for (int i = 0; i < 2; i++) {
        int idx = t + i * 256;
        int rr = idx >> 6, d = idx & 63;
        float s = part[0][rr][d] + part[1][rr][d] + part[2][rr][d] + part[3][rr][d];
        aout[((size_t)(b * Sx + q0 + rr)) * Dx + h * HDx + d] = s;
    }
}

// ---------------------------------------------------------------------------
extern "C" void kernel_launch(void* const* d_in, const int* in_sizes, int n_in,
                              void* d_out, int out_size) {
    const float* x      = (const float*)d_in[0];
    const float* mask   = (const float*)d_in[1];
    const float* w_attn = (const float*)d_in[2];
    const float* b_attn = (const float*)d_in[3];
    const float* w_proj = (const float*)d_in[4];
    const float* b_proj = (const float*)d_in[5];

    float* out_a = (float*)d_out;
    float* out_w = (float*)d_out + (size_t)Bx * Sx * Dx;

    float *qkv, *aout, *xr, *war, *wpr;
    cudaGetSymbolAddress((void**)&qkv,  g_qkv);
    cudaGetSymbolAddress((void**)&aout, g_aout);
    cudaGetSymbolAddress((void**)&xr,   g_xr);
    cudaGetSymbolAddress((void**)&war,  g_war);
    cudaGetSymbolAddress((void**)&wpr,  g_wpr);

    // Pre-round inputs to tf32 bit patterns
    {
        int n;
        n = Bx * Sx * Dx / 4;  round_tf32<<<(n + 255) / 256, 256>>>(x, xr, n);
        n = Dx * TDx / 4;      round_tf32<<<(n + 255) / 256, 256>>>(w_attn, war, n);
        n = Dx * Dx / 4;       round_tf32<<<(n + 255) / 256, 256>>>(w_proj, wpr, n);
    }
    // K1: qkv = x @ w_attn + b_attn  (tf32 tensor cores)
    {
        dim3 grid(TDx / 128, (Bx * Sx) / 128);
        gemm_mma<<<grid, 256>>>(xr, war, b_attn, qkv, Bx * Sx, TDx, Dx);
    }
    // K2: attention
    {
        dim3 grid(Sx / QT, Hx, Bx);
        attn_kernel<<<grid, 256>>>(qkv, mask, out_w, aout);
    }
    // K3: a = aout @ w_proj + b_proj (aout fed raw; hw truncates to tf32)
    {
        dim3 grid(Dx / 128, (Bx * Sx) / 128);
        gemm_mma<<<grid, 256>>>(aout, wpr, b_proj, out_a, Bx * Sx, Dx, Dx);
    }
}

// round 5
// speedup vs baseline: 2.0993x; 1.2656x over previous
#include <cuda_runtime.h>
#include <cuda_bf16.h>
#include <math.h>

#define Bx 4
#define Sx 1024
#define Dx 1024
#define Hx 16
#define HDx 64
#define TDx 3072
#define SCS 1028   // scores smem row stride (== 4 mod 32 -> conflict-free frags)

__device__ float g_qkv[Bx * Sx * TDx];
__device__ float g_aout[Bx * Sx * Dx];
__device__ float g_xr[Bx * Sx * Dx];
__device__ float g_war[Dx * TDx];
__device__ float g_wpr[Dx * Dx];   // w_proj hi (tf32)
__device__ float g_wpl[Dx * Dx];   // w_proj lo (tf32 of residual)

// ---------------------------------------------------------------------------
__device__ __forceinline__ unsigned f2tf32(float f) {
    unsigned r;
    asm("cvt.rna.tf32.f32 %0, %1;" : "=r"(r) : "f"(f));
    return r;
}
__device__ __forceinline__ float tf32f(float f) { return __uint_as_float(f2tf32(f)); }

__device__ __forceinline__ void mma_tf32(float c[4], const unsigned a[4], const unsigned b[2]) {
    asm volatile("mma.sync.aligned.m16n8k8.row.col.f32.tf32.tf32.f32 "
        "{%0,%1,%2,%3}, {%4,%5,%6,%7}, {%8,%9}, {%0,%1,%2,%3};"
        : "+f"(c[0]), "+f"(c[1]), "+f"(c[2]), "+f"(c[3])
        : "r"(a[0]), "r"(a[1]), "r"(a[2]), "r"(a[3]), "r"(b[0]), "r"(b[1]));
}

// FFMA-only exp (no MUFU): exp(x) = 2^(x*log2e), deg-5 poly on [-0.5,0.5]
__device__ __forceinline__ float expapx(float x) {
    float y = fmaxf(x * 1.4426950408889634f, -80.f);
    float t = y + 12582912.f;
    int   n = __float_as_int(t) - 0x4b400000;
    float f = y - (t - 12582912.f);
    float p = 1.3333558146428443e-3f;
    p = fmaf(p, f, 9.618129842118066e-3f);
    p = fmaf(p, f, 5.550410866482158e-2f);
    p = fmaf(p, f, 2.402265069591007e-1f);
    p = fmaf(p, f, 6.931471805599453e-1f);
    p = fmaf(p, f, 1.0f);
    return __int_as_float(__float_as_int(p) + (n << 23));
}

#define CP16(dst, src) asm volatile("cp.async.cg.shared.global [%0], [%1], 16;" :: "r"(dst), "l"(src))
#define CP_COMMIT()    asm volatile("cp.async.commit_group;")
#define CP_WAIT1()     asm volatile("cp.async.wait_group 1;")
#define CP_WAIT0()     asm volatile("cp.async.wait_group 0;")

// ---------------------------------------------------------------------------
__global__ void round_tf32(const float* __restrict__ in, float* __restrict__ out, int n4) {
    int i = blockIdx.x * blockDim.x + threadIdx.x;
    if (i < n4) {
        float4 v = ((const float4*)in)[i];
        uint4 o;
        o.x = f2tf32(v.x); o.y = f2tf32(v.y); o.z = f2tf32(v.z); o.w = f2tf32(v.w);
        ((uint4*)out)[i] = o;
    }
}

// split x = hi + lo (both tf32-representable)
__global__ void round_split(const float* __restrict__ in, float* __restrict__ hi,
                            float* __restrict__ lo, int n4) {
    int i = blockIdx.x * blockDim.x + threadIdx.x;
    if (i < n4) {
        float4 v = ((const float4*)in)[i];
        float4 h, l;
        h.x = tf32f(v.x); l.x = tf32f(v.x - h.x);
        h.y = tf32f(v.y); l.y = tf32f(v.y - h.y);
        h.z = tf32f(v.z); l.z = tf32f(v.z - h.z);
        h.w = tf32f(v.w); l.w = tf32f(v.w - h.w);
        ((float4*)hi)[i] = h;
        ((float4*)lo)[i] = l;
    }
}

// ---------------------------------------------------------------------------
// tf32 GEMM: C = A@B + bias, 128x128 tiles (A,B pre-rounded tf32 bits)
// ---------------------------------------------------------------------------
__global__ __launch_bounds__(256) void gemm_mma(const float* __restrict__ A,
                                                const float* __restrict__ B,
                                                const float* __restrict__ bias,
                                                float* __restrict__ C,
                                                int M, int N, int K) {
    __shared__ float As[2][128][20];
    __shared__ float Bs[2][16][136];

    const int t = threadIdx.x;
    const int warp = t >> 5, lane = t & 31;
    const int wm = warp >> 2, wn = warp & 3;
    const int r = lane >> 2, cq = lane & 3;
    const int row0 = blockIdx.y * 128, col0 = blockIdx.x * 128;

    float acc[4][4][4];
    #pragma unroll
    for (int i = 0; i < 4; i++)
        #pragma unroll
        for (int j = 0; j < 4; j++)
            #pragma unroll
            for (int k = 0; k < 4; k++) acc[i][j][k] = 0.f;

    const int aM0 = (t * 2) >> 2,  aK0 = (t * 2) & 3;
    const int aM1 = (t * 2 + 1) >> 2, aK1 = (t * 2 + 1) & 3;
    const int bK0 = (t * 2) >> 5,  bN0 = (t * 2) & 31;
    const int bK1 = (t * 2 + 1) >> 5, bN1 = (t * 2 + 1) & 31;

    auto loadG = [&](int buf, int k0) {
        unsigned da0 = (unsigned)__cvta_generic_to_shared(&As[buf][aM0][aK0 * 4]);
        unsigned da1 = (unsigned)__cvta_generic_to_shared(&As[buf][aM1][aK1 * 4]);
        CP16(da0, &A[(size_t)(row0 + aM0) * K + k0 + aK0 * 4]);
        CP16(da1, &A[(size_t)(row0 + aM1) * K + k0 + aK1 * 4]);
        unsigned db0 = (unsigned)__cvta_generic_to_shared(&Bs[buf][bK0][bN0 * 4]);
        unsigned db1 = (unsigned)__cvta_generic_to_shared(&Bs[buf][bK1][bN1 * 4]);
        CP16(db0, &B[(size_t)(k0 + bK0) * N + col0 + bN0 * 4]);
        CP16(db1, &B[(size_t)(k0 + bK1) * N + col0 + bN1 * 4]);
    };

    loadG(0, 0);
    CP_COMMIT();

    const int NT = K / 16;
    for (int kt = 0; kt < NT; kt++) {
        int buf = kt & 1;
        if (kt + 1 < NT) { loadG((kt + 1) & 1, (kt + 1) * 16); CP_COMMIT(); CP_WAIT1(); }
        else             { CP_WAIT0(); }
        __syncthreads();

        #pragma unroll
        for (int ks = 0; ks < 2; ks++) {
            const int kb = ks * 8;
            unsigned a[4][4], b[4][2];
            #pragma unroll
            for (int mm = 0; mm < 4; mm++) {
                const float* ap0 = &As[buf][wm * 64 + mm * 16 + r][kb + cq];
                const float* ap1 = ap0 + 8 * 20;
                a[mm][0] = __float_as_uint(ap0[0]);
                a[mm][1] = __float_as_uint(ap1[0]);
                a[mm][2] = __float_as_uint(ap0[4]);
                a[mm][3] = __float_as_uint(ap1[4]);
            }
            #pragma unroll
            for (int nn = 0; nn < 4; nn++) {
                const float* bp = &Bs[buf][kb + cq][wn * 32 + nn * 8 + r];
                b[nn][0] = __float_as_uint(bp[0]);
                b[nn][1] = __float_as_uint(bp[4 * 136]);
            }
            #pragma unroll
            for (int mm = 0; mm < 4; mm++)
                #pragma unroll
                for (int nn = 0; nn < 4; nn++)
                    mma_tf32(acc[mm][nn], a[mm], b[nn]);
        }
        __syncthreads();
    }

    #pragma unroll
    for (int mm = 0; mm < 4; mm++) {
        int r0 = row0 + wm * 64 + mm * 16 + r;
        #pragma unroll
        for (int nn = 0; nn < 4; nn++) {
            int c0 = col0 + wn * 32 + nn * 8 + 2 * cq;
            float2 bv = *(const float2*)&bias[c0];
            float2 o0 = {acc[mm][nn][0] + bv.x, acc[mm][nn][1] + bv.y};
            float2 o1 = {acc[mm][nn][2] + bv.x, acc[mm][nn][3] + bv.y};
            *(float2*)&C[(size_t)r0 * N + c0] = o0;
            *(float2*)&C[(size_t)(r0 + 8) * N + c0] = o1;
        }
    }
}

// ---------------------------------------------------------------------------
// 3xTF32 split GEMM: C = A@B + bias, near-fp32 accuracy.
// A raw fp32 (split in-register), B pre-split into Bh_/Bl_.
// ---------------------------------------------------------------------------
__global__ __launch_bounds__(256) void gemm_mma_split(const float* __restrict__ A,
                                                      const float* __restrict__ Bh_,
                                                      const float* __restrict__ Bl_,
                                                      const float* __restrict__ bias,
                                                      float* __restrict__ C,
                                                      int M, int N, int K) {
    __shared__ float As[2][128][20];
    __shared__ float Bh[2][16][136];
    __shared__ float Bl[2][16][136];

    const int t = threadIdx.x;
    const int warp = t >> 5, lane = t & 31;
    const int wm = warp >> 2, wn = warp & 3;
    const int r = lane >> 2, cq = lane & 3;
    const int row0 = blockIdx.y * 128, col0 = blockIdx.x * 128;

    float acc[4][4][4];
    #pragma unroll
    for (int i = 0; i < 4; i++)
        #pragma unroll
        for (int j = 0; j < 4; j++)
            #pragma unroll
            for (int k = 0; k < 4; k++) acc[i][j][k] = 0.f;

    const int aM0 = (t * 2) >> 2,  aK0 = (t * 2) & 3;
    const int aM1 = (t * 2 + 1) >> 2, aK1 = (t * 2 + 1) & 3;
    const int bK0 = (t * 2) >> 5,  bN0 = (t * 2) & 31;
    const int bK1 = (t * 2 + 1) >> 5, bN1 = (t * 2 + 1) & 31;

    auto loadG = [&](int buf, int k0) {
        unsigned da0 = (unsigned)__cvta_generic_to_shared(&As[buf][aM0][aK0 * 4]);
        unsigned da1 = (unsigned)__cvta_generic_to_shared(&As[buf][aM1][aK1 * 4]);
        CP16(da0, &A[(size_t)(row0 + aM0) * K + k0 + aK0 * 4]);
        CP16(da1, &A[(size_t)(row0 + aM1) * K + k0 + aK1 * 4]);
        unsigned dh0 = (unsigned)__cvta_generic_to_shared(&Bh[buf][bK0][bN0 * 4]);
        unsigned dh1 = (unsigned)__cvta_generic_to_shared(&Bh[buf][bK1][bN1 * 4]);
        CP16(dh0, &Bh_[(size_t)(k0 + bK0) * N + col0 + bN0 * 4]);
        CP16(dh1, &Bh_[(size_t)(k0 + bK1) * N + col0 + bN1 * 4]);
        unsigned dl0 = (unsigned)__cvta_generic_to_shared(&Bl[buf][bK0][bN0 * 4]);
        unsigned dl1 = (unsigned)__cvta_generic_to_shared(&Bl[buf][bK1][bN1 * 4]);
        CP16(dl0, &Bl_[(size_t)(k0 + bK0) * N + col0 + bN0 * 4]);
        CP16(dl1, &Bl_[(size_t)(k0 + bK1) * N + col0 + bN1 * 4]);
    };

    loadG(0, 0);
    CP_COMMIT();

    const int NT = K / 16;
    for (int kt = 0; kt < NT; kt++) {
        int buf = kt & 1;
        if (kt + 1 < NT) { loadG((kt + 1) & 1, (kt + 1) * 16); CP_COMMIT(); CP_WAIT1(); }
        else             { CP_WAIT0(); }
        __syncthreads();

        #pragma unroll
        for (int ks = 0; ks < 2; ks++) {
            const int kb = ks * 8;
            unsigned bh[4][2], bl[4][2];
            #pragma unroll
            for (int nn = 0; nn < 4; nn++) {
                const float* bph = &Bh[buf][kb + cq][wn * 32 + nn * 8 + r];
                bh[nn][0] = __float_as_uint(bph[0]);
                bh[nn][1] = __float_as_uint(bph[4 * 136]);
                const float* bpl = &Bl[buf][kb + cq][wn * 32 + nn * 8 + r];
                bl[nn][0] = __float_as_uint(bpl[0]);
                bl[nn][1] = __float_as_uint(bpl[4 * 136]);
            }
            #pragma unroll
            for (int mm = 0; mm < 4; mm++) {
                const float* ap0 = &As[buf][wm * 64 + mm * 16 + r][kb + cq];
                const float* ap1 = ap0 + 8 * 20;
                float av[4] = {ap0[0], ap1[0], ap0[4], ap1[4]};
                unsigned ah[4], al[4];
                #pragma unroll
                for (int e = 0; e < 4; e++) {
                    ah[e] = f2tf32(av[e]);
                    al[e] = f2tf32(av[e] - __uint_as_float(ah[e]));
                }
                #pragma unroll
                for (int nn = 0; nn < 4; nn++) {
                    mma_tf32(acc[mm][nn], al, bh[nn]);
                    mma_tf32(acc[mm][nn], ah, bl[nn]);
                    mma_tf32(acc[mm][nn], ah, bh[nn]);
                }
            }
        }
        __syncthreads();
    }

    #pragma unroll
    for (int mm = 0; mm < 4; mm++) {
        int r0 = row0 + wm * 64 + mm * 16 + r;
        #pragma unroll
        for (int nn = 0; nn < 4; nn++) {
            int c0 = col0 + wn * 32 + nn * 8 + 2 * cq;
            float2 bv = *(const float2*)&bias[c0];
            float2 o0 = {acc[mm][nn][0] + bv.x, acc[mm][nn][1] + bv.y};
            float2 o1 = {acc[mm][nn][2] + bv.x, acc[mm][nn][3] + bv.y};
            *(float2*)&C[(size_t)r0 * N + c0] = o0;
            *(float2*)&C[(size_t)(r0 + 8) * N + c0] = o1;
        }
    }
}

// ---------------------------------------------------------------------------
// Tensor-core attention (R4 layout, unbiased rounding everywhere):
// p rounded to tf32 after exp; V rounded at staging.
// ---------------------------------------------------------------------------
__global__ __launch_bounds__(256) void attn_mma(const float* __restrict__ qkv,
                                                const float* __restrict__ mask,
                                                float* __restrict__ w_out,
                                                float* __restrict__ aout) {
    extern __shared__ float sm[];
    float* sc   = sm;
    float* qs   = sm + 32896;
    float* kv   = sm + 35072;
    float* mks  = sm + 43776;
    float* invs = sm + 44800;

    const int q0 = blockIdx.x * 32;
    const int h  = blockIdx.y;
    const int b  = blockIdx.z;
    const int t  = threadIdx.x;
    const int warp = t >> 5, lane = t & 31;
    const int r = lane >> 2, cq = lane & 3;
    const int wm = warp >> 2, wn = warp & 3;
    const float* base = qkv + (size_t)b * Sx * TDx;

    *(float4*)&mks[4 * t] = *(const float4*)&mask[b * Sx + 4 * t];
    #pragma unroll
    for (int i = 0; i < 8; i++) {
        int id = t + i * 256;
        int rr = id >> 6, d = id & 63;
        qs[rr * 68 + d] = tf32f(base[(size_t)(q0 + rr) * TDx + h * HDx + d]);
    }

    const int ntile = (q0 + 31) / 128 + 1;
    const int Ccols = ntile * 128;

    // ---- scores ----
    for (int jt = 0; jt < ntile; jt++) {
        const int j0 = jt * 128;
        #pragma unroll
        for (int i = 0; i < 8; i++) {
            int id = t + i * 256;
            int jj = id >> 4, d0 = (id & 15) * 4;
            float4 v = *(const float4*)&base[(size_t)(j0 + jj) * TDx + Dx + h * HDx + d0];
            float* dst = &kv[jj * 68 + d0];
            dst[0] = tf32f(v.x); dst[1] = tf32f(v.y); dst[2] = tf32f(v.z); dst[3] = tf32f(v.w);
        }
        __syncthreads();

        float c[4][4];
        #pragma unroll
        for (int i = 0; i < 4; i++)
            #pragma unroll
            for (int j = 0; j < 4; j++) c[i][j] = 0.f;

        #pragma unroll
        for (int ks = 0; ks < 8; ks++) {
            const int kb = ks * 8;
            unsigned a[4];
            const float* ap0 = &qs[(wm * 16 + r) * 68 + kb + cq];
            const float* ap1 = ap0 + 8 * 68;
            a[0] = __float_as_uint(ap0[0]);
            a[1] = __float_as_uint(ap1[0]);
            a[2] = __float_as_uint(ap0[4]);
            a[3] = __float_as_uint(ap1[4]);
            #pragma unroll
            for (int nn = 0; nn < 4; nn++) {
                const float* bp = &kv[(wn * 32 + nn * 8 + r) * 68 + kb + cq];
                unsigned bf[2] = {__float_as_uint(bp[0]), __float_as_uint(bp[4])};
                mma_tf32(c[nn], a, bf);
            }
        }

        const int qa = q0 + wm * 16 + r;
        const int qb = qa + 8;
        #pragma unroll
        for (int nn = 0; nn < 4; nn++) {
            int jl = wn * 32 + nn * 8 + 2 * cq;
            int jg = j0 + jl;
            float mk0 = mks[jg], mk1 = mks[jg + 1];
            float* s0 = &sc[(wm * 16 + r) * SCS + jg];
            float* s1 = &sc[(wm * 16 + r + 8) * SCS + jg];
            s0[0] = (jg     <= qa) ? tf32f(expapx(fmaf(c[nn][0], 0.125f, mk0))) : 0.f;
            s0[1] = (jg + 1 <= qa) ? tf32f(expapx(fmaf(c[nn][1], 0.125f, mk1))) : 0.f;
            s1[0] = (jg     <= qb) ? tf32f(expapx(fmaf(c[nn][2], 0.125f, mk0))) : 0.f;
            s1[1] = (jg + 1 <= qb) ? tf32f(expapx(fmaf(c[nn][3], 0.125f, mk1))) : 0.f;
        }
        __syncthreads();
    }

    // ---- rowsum + normalized w store + zero fill ----
    #pragma unroll
    for (int rr = 0; rr < 4; rr++) {
        int row = warp * 4 + rr;
        int q = q0 + row;
        float s = 0.f;
        for (int j4 = lane * 4; j4 < Ccols; j4 += 128) {
            float4 v = *(float4*)&sc[row * SCS + j4];
            s += v.x + v.y + v.z + v.w;
        }
        #pragma unroll
        for (int o = 16; o > 0; o >>= 1) s += __shfl_xor_sync(0xffffffffu, s, o);
        float inv = 1.f / s;
        if (lane == 0) invs[row] = inv;
        size_t wb = ((size_t)((b * Hx + h) * Sx + q)) * Sx;
        for (int j4 = lane * 4; j4 < Ccols; j4 += 128) {
            float4 v = *(float4*)&sc[row * SCS + j4];
            float4 o4 = {v.x * inv, v.y * inv, v.z * inv, v.w * inv};
            *(float4*)&w_out[wb + j4] = o4;
        }
        float4 z = {0.f, 0.f, 0.f, 0.f};
        for (int j4 = Ccols + lane * 4; j4 < Sx; j4 += 128)
            *(float4*)&w_out[wb + j4] = z;
    }
    __syncthreads();

    // ---- PV ----
    float oc[2][4];
    #pragma unroll
    for (int i = 0; i < 2; i++)
        #pragma unroll
        for (int j = 0; j < 4; j++) oc[i][j] = 0.f;

    for (int jt = 0; jt < ntile; jt++) {
        const int j0 = jt * 128;
        #pragma unroll
        for (int i = 0; i < 8; i++) {
            int id = t + i * 256;
            int jj = id & 127, d0 = (id >> 7) * 4;
            float4 v = *(const float4*)&base[(size_t)(j0 + jj) * TDx + 2 * Dx + h * HDx + d0];
            kv[(d0 + 0) * 132 + jj] = tf32f(v.x);
            kv[(d0 + 1) * 132 + jj] = tf32f(v.y);
            kv[(d0 + 2) * 132 + jj] = tf32f(v.z);
            kv[(d0 + 3) * 132 + jj] = tf32f(v.w);
        }
        __syncthreads();

        #pragma unroll
        for (int ks = 0; ks < 16; ks++) {
            const int kb = ks * 8;
            unsigned a[4];
            const float* ap0 = &sc[(wm * 16 + r) * SCS + j0 + kb + cq];
            const float* ap1 = ap0 + 8 * SCS;
            a[0] = __float_as_uint(ap0[0]);
            a[1] = __float_as_uint(ap1[0]);
            a[2] = __float_as_uint(ap0[4]);
            a[3] = __float_as_uint(ap1[4]);
            #pragma unroll
            for (int nn = 0; nn < 2; nn++) {
                const float* bp = &kv[(wn * 16 + nn * 8 + r) * 132 + kb + cq];
                unsigned bf[2] = {__float_as_uint(bp[0]), __float_as_uint(bp[4])};
                mma_tf32(oc[nn], a, bf);
            }
        }
        __syncthreads();
    }

    {
        int row_a = wm * 16 + r, row_b = row_a + 8;
        float ia = invs[row_a], ib = invs[row_b];
        #pragma unroll
        for (int nn = 0; nn < 2; nn++) {
            int d = wn * 16 + nn * 8 + 2 * cq;
            size_t ra = ((size_t)(b * Sx + q0 + row_a)) * Dx + h * HDx + d;
            size_t rb = ((size_t)(b * Sx + q0 + row_b)) * Dx + h * HDx + d;
            float2 v0 = {oc[nn][0] * ia, oc[nn][1] * ia};
            float2 v1 = {oc[nn][2] * ib, oc[nn][3] * ib};
            *(float2*)&aout[ra] = v0;
            *(float2*)&aout[rb] = v1;
        }
    }
}

// ---------------------------------------------------------------------------
extern "C" void kernel_launch(void* const* d_in, const int* in_sizes, int n_in,
                              void* d_out, int out_size) {
    const float* x      = (const float*)d_in[0];
    const float* mask   = (const float*)d_in[1];
    const float* w_attn = (const float*)d_in[2];
    const float* b_attn = (const float*)d_in[3];
    const float* w_proj = (const float*)d_in[4];
    const float* b_proj = (const float*)d_in[5];

    float* out_a = (float*)d_out;
    float* out_w = (float*)d_out + (size_t)Bx * Sx * Dx;

    float *qkv, *aout, *xr, *war, *wpr, *wpl;
    cudaGetSymbolAddress((void**)&qkv,  g_qkv);
    cudaGetSymbolAddress((void**)&aout, g_aout);
    cudaGetSymbolAddress((void**)&xr,   g_xr);
    cudaGetSymbolAddress((void**)&war,  g_war);
    cudaGetSymbolAddress((void**)&wpr,  g_wpr);
    cudaGetSymbolAddress((void**)&wpl,  g_wpl);

    static const int ATTN_SMEM = 44832 * 4;
    cudaFuncSetAttribute(attn_mma, cudaFuncAttributeMaxDynamicSharedMemorySize, ATTN_SMEM);

    {
        int n;
        n = Bx * Sx * Dx / 4;  round_tf32<<<(n + 255) / 256, 256>>>(x, xr, n);
        n = Dx * TDx / 4;      round_tf32<<<(n + 255) / 256, 256>>>(w_attn, war, n);
        n = Dx * Dx / 4;       round_split<<<(n + 255) / 256, 256>>>(w_proj, wpr, wpl, n);
    }
    {
        dim3 grid(TDx / 128, (Bx * Sx) / 128);
        gemm_mma<<<grid, 256>>>(xr, war, b_attn, qkv, Bx * Sx, TDx, Dx);
    }
    {
        dim3 grid(Sx / 32, Hx, Bx);
        attn_mma<<<grid, 256, ATTN_SMEM>>>(qkv, mask, out_w, aout);
    }
    {
        dim3 grid(Dx / 128, (Bx * Sx) / 128);
        gemm_mma_split<<<grid, 256>>>(aout, wpr, wpl, b_proj, out_a, Bx * Sx, Dx, Dx);
    }
}

// round 6
// speedup vs baseline: 2.8883x; 1.3758x over previous
#include <cuda_runtime.h>
#include <cuda_bf16.h>
#include <math.h>

#define Bx 4
#define Sx 1024
#define Dx 1024
#define Hx 16
#define HDx 64
#define TDx 3072
#define SCS 1028   // scores smem row stride (== 4 mod 32 -> conflict-free frags)

__device__ float g_qkv[Bx * Sx * TDx];
__device__ float g_aout[Bx * Sx * Dx];
__device__ float g_xr[Bx * Sx * Dx];
__device__ float g_war[Dx * TDx];
__device__ float g_wpr[Dx * Dx];
__device__ float g_kT[Bx * Hx * Sx * HDx];   // [bh][j][d] tf32-rounded K
__device__ float g_vT[Bx * Hx * HDx * Sx];   // [bh][d][j] tf32-rounded V^T

// ---------------------------------------------------------------------------
__device__ __forceinline__ unsigned f2tf32(float f) {
    unsigned r;
    asm("cvt.rna.tf32.f32 %0, %1;" : "=r"(r) : "f"(f));
    return r;
}
__device__ __forceinline__ float tf32f(float f) { return __uint_as_float(f2tf32(f)); }

__device__ __forceinline__ void mma_tf32(float c[4], const unsigned a[4], const unsigned b[2]) {
    asm volatile("mma.sync.aligned.m16n8k8.row.col.f32.tf32.tf32.f32 "
        "{%0,%1,%2,%3}, {%4,%5,%6,%7}, {%8,%9}, {%0,%1,%2,%3};"
        : "+f"(c[0]), "+f"(c[1]), "+f"(c[2]), "+f"(c[3])
        : "r"(a[0]), "r"(a[1]), "r"(a[2]), "r"(a[3]), "r"(b[0]), "r"(b[1]));
}

// FFMA-only exp: exp(x) = 2^(x*log2e), deg-5 poly on [-0.5,0.5]
__device__ __forceinline__ float expapx(float x) {
    float y = fmaxf(x * 1.4426950408889634f, -80.f);
    float t = y + 12582912.f;
    int   n = __float_as_int(t) - 0x4b400000;
    float f = y - (t - 12582912.f);
    float p = 1.3333558146428443e-3f;
    p = fmaf(p, f, 9.618129842118066e-3f);
    p = fmaf(p, f, 5.550410866482158e-2f);
    p = fmaf(p, f, 2.402265069591007e-1f);
    p = fmaf(p, f, 6.931471805599453e-1f);
    p = fmaf(p, f, 1.0f);
    return __int_as_float(__float_as_int(p) + (n << 23));
}

#define CP16(dst, src) asm volatile("cp.async.cg.shared.global [%0], [%1], 16;" :: "r"(dst), "l"(src))
#define CP_COMMIT()    asm volatile("cp.async.commit_group;")
#define CP_WAIT1()     asm volatile("cp.async.wait_group 1;")
#define CP_WAIT0()     asm volatile("cp.async.wait_group 0;")

// ---------------------------------------------------------------------------
__global__ void round_tf32(const float* __restrict__ in, float* __restrict__ out, int n4) {
    int i = blockIdx.x * blockDim.x + threadIdx.x;
    if (i < n4) {
        float4 v = ((const float4*)in)[i];
        uint4 o;
        o.x = f2tf32(v.x); o.y = f2tf32(v.y); o.z = f2tf32(v.z); o.w = f2tf32(v.w);
        ((uint4*)out)[i] = o;
    }
}

// kT[bh][j][d] = tf32(K) — fully coalesced both sides
__global__ void prep_kT(const float* __restrict__ qkv, float* __restrict__ kT) {
    int i = blockIdx.x * 256 + threadIdx.x;     // 1,048,576 chunks
    int c = i & 15, j = (i >> 4) & 1023, bh = i >> 14;
    int b = bh >> 4, h = bh & 15;
    float4 v = *(const float4*)&qkv[((size_t)(b * Sx + j)) * TDx + Dx + h * HDx + c * 4];
    uint4 o = {f2tf32(v.x), f2tf32(v.y), f2tf32(v.z), f2tf32(v.w)};
    *(uint4*)&kT[(size_t)i * 4] = o;
}

// vT[bh][d][j] = tf32(V) — smem tile transpose, coalesced both sides
__global__ void prep_vT(const float* __restrict__ qkv, float* __restrict__ vT) {
    __shared__ float tile[64][68];
    int bh = blockIdx.y, j0 = blockIdx.x * 64;
    int b = bh >> 4, h = bh & 15;
    int t = threadIdx.x;
    #pragma unroll
    for (int i = 0; i < 4; i++) {
        int id = t + i * 256;
        int jj = id >> 4, c = id & 15;
        float4 v = *(const float4*)&qkv[((size_t)(b * Sx + j0 + jj)) * TDx + 2 * Dx + h * HDx + c * 4];
        tile[jj][c * 4 + 0] = tf32f(v.x);
        tile[jj][c * 4 + 1] = tf32f(v.y);
        tile[jj][c * 4 + 2] = tf32f(v.z);
        tile[jj][c * 4 + 3] = tf32f(v.w);
    }
    __syncthreads();
    #pragma unroll
    for (int i = 0; i < 4; i++) {
        int id = t + i * 256;
        int d = id >> 4, c = id & 15;
        float4 o = {tile[c * 4 + 0][d], tile[c * 4 + 1][d], tile[c * 4 + 2][d], tile[c * 4 + 3][d]};
        *(float4*)&vT[((size_t)(bh * HDx + d)) * Sx + j0 + c * 4] = o;
    }
}

// ---------------------------------------------------------------------------
// tf32 GEMM: C = A@B + bias, 128x128 tiles (A,B pre-rounded tf32 bits)
// ---------------------------------------------------------------------------
__global__ __launch_bounds__(256) void gemm_mma(const float* __restrict__ A,
                                                const float* __restrict__ B,
                                                const float* __restrict__ bias,
                                                float* __restrict__ C,
                                                int M, int N, int K) {
    __shared__ float As[2][128][20];
    __shared__ float Bs[2][16][136];

    const int t = threadIdx.x;
    const int warp = t >> 5, lane = t & 31;
    const int wm = warp >> 2, wn = warp & 3;
    const int r = lane >> 2, cq = lane & 3;
    const int row0 = blockIdx.y * 128, col0 = blockIdx.x * 128;

    float acc[4][4][4];
    #pragma unroll
    for (int i = 0; i < 4; i++)
        #pragma unroll
        for (int j = 0; j < 4; j++)
            #pragma unroll
            for (int k = 0; k < 4; k++) acc[i][j][k] = 0.f;

    const int aM0 = (t * 2) >> 2,  aK0 = (t * 2) & 3;
    const int aM1 = (t * 2 + 1) >> 2, aK1 = (t * 2 + 1) & 3;
    const int bK0 = (t * 2) >> 5,  bN0 = (t * 2) & 31;
    const int bK1 = (t * 2 + 1) >> 5, bN1 = (t * 2 + 1) & 31;

    auto loadG = [&](int buf, int k0) {
        unsigned da0 = (unsigned)__cvta_generic_to_shared(&As[buf][aM0][aK0 * 4]);
        unsigned da1 = (unsigned)__cvta_generic_to_shared(&As[buf][aM1][aK1 * 4]);
        CP16(da0, &A[(size_t)(row0 + aM0) * K + k0 + aK0 * 4]);
        CP16(da1, &A[(size_t)(row0 + aM1) * K + k0 + aK1 * 4]);
        unsigned db0 = (unsigned)__cvta_generic_to_shared(&Bs[buf][bK0][bN0 * 4]);
        unsigned db1 = (unsigned)__cvta_generic_to_shared(&Bs[buf][bK1][bN1 * 4]);
        CP16(db0, &B[(size_t)(k0 + bK0) * N + col0 + bN0 * 4]);
        CP16(db1, &B[(size_t)(k0 + bK1) * N + col0 + bN1 * 4]);
    };

    loadG(0, 0);
    CP_COMMIT();

    const int NT = K / 16;
    for (int kt = 0; kt < NT; kt++) {
        int buf = kt & 1;
        if (kt + 1 < NT) { loadG((kt + 1) & 1, (kt + 1) * 16); CP_COMMIT(); CP_WAIT1(); }
        else             { CP_WAIT0(); }
        __syncthreads();

        #pragma unroll
        for (int ks = 0; ks < 2; ks++) {
            const int kb = ks * 8;
            unsigned a[4][4], b[4][2];
            #pragma unroll
            for (int mm = 0; mm < 4; mm++) {
                const float* ap0 = &As[buf][wm * 64 + mm * 16 + r][kb + cq];
                const float* ap1 = ap0 + 8 * 20;
                a[mm][0] = __float_as_uint(ap0[0]);
                a[mm][1] = __float_as_uint(ap1[0]);
                a[mm][2] = __float_as_uint(ap0[4]);
                a[mm][3] = __float_as_uint(ap1[4]);
            }
            #pragma unroll
            for (int nn = 0; nn < 4; nn++) {
                const float* bp = &Bs[buf][kb + cq][wn * 32 + nn * 8 + r];
                b[nn][0] = __float_as_uint(bp[0]);
                b[nn][1] = __float_as_uint(bp[4 * 136]);
            }
            #pragma unroll
            for (int mm = 0; mm < 4; mm++)
                #pragma unroll
                for (int nn = 0; nn < 4; nn++)
                    mma_tf32(acc[mm][nn], a[mm], b[nn]);
        }
        __syncthreads();
    }

    #pragma unroll
    for (int mm = 0; mm < 4; mm++) {
        int r0 = row0 + wm * 64 + mm * 16 + r;
        #pragma unroll
        for (int nn = 0; nn < 4; nn++) {
            int c0 = col0 + wn * 32 + nn * 8 + 2 * cq;
            float2 bv = *(const float2*)&bias[c0];
            float2 o0 = {acc[mm][nn][0] + bv.x, acc[mm][nn][1] + bv.y};
            float2 o1 = {acc[mm][nn][2] + bv.x, acc[mm][nn][3] + bv.y};
            *(float2*)&C[(size_t)r0 * N + c0] = o0;
            *(float2*)&C[(size_t)(r0 + 8) * N + c0] = o1;
        }
    }
}

// ---------------------------------------------------------------------------
// Tensor-core attention; K/V tiles staged from pre-rounded kT/vT via cp.async
// (double-buffered). CTA = 32 q-rows of one (b,h).
// Dynamic smem (floats):
//   sc   [32][SCS]      @ 0       (32896)
//   qs   [32][68]       @ 32896   (2176)
//   kv   2 x 8704       @ 35072   (17408)  K tile [128][68] / V tile [64][132]
//   mks  [1024]         @ 52480
//   invs [32]           @ 53504   -> total 53536 floats = 214144 B
// ---------------------------------------------------------------------------
__global__ __launch_bounds__(256) void attn_mma(const float* __restrict__ qkv,
                                                const float* __restrict__ kT,
                                                const float* __restrict__ vT,
                                                const float* __restrict__ mask,
                                                float* __restrict__ w_out,
                                                float* __restrict__ aout) {
    extern __shared__ float sm[];
    float* sc   = sm;
    float* qs   = sm + 32896;
    float* kvb  = sm + 35072;   // two buffers of 8704
    float* mks  = sm + 52480;
    float* invs = sm + 53504;

    const int q0 = blockIdx.x * 32;
    const int h  = blockIdx.y;
    const int b  = blockIdx.z;
    const int bh = b * Hx + h;
    const int t  = threadIdx.x;
    const int warp = t >> 5, lane = t & 31;
    const int r = lane >> 2, cq = lane & 3;
    const int wm = warp >> 2, wn = warp & 3;
    const float* base = qkv + (size_t)b * Sx * TDx;
    const float* kTb = kT + (size_t)bh * Sx * HDx;
    const float* vTb = vT + (size_t)bh * HDx * Sx;

    // K tile stage: 128 rows x 16 chunks; V tile stage: 64 rows x 32 chunks
    auto stageK = [&](int buf, int j0) {
        float* dstb = kvb + buf * 8704;
        #pragma unroll
        for (int i = 0; i < 8; i++) {
            int id = t + i * 256;
            int jj = id >> 4, c = id & 15;
            unsigned d = (unsigned)__cvta_generic_to_shared(&dstb[jj * 68 + c * 4]);
            CP16(d, &kTb[(size_t)(j0 + jj) * HDx + c * 4]);
        }
    };
    auto stageV = [&](int buf, int j0) {
        float* dstb = kvb + buf * 8704;
        #pragma unroll
        for (int i = 0; i < 8; i++) {
            int id = t + i * 256;
            int dd = id >> 5, c = id & 31;
            unsigned d = (unsigned)__cvta_generic_to_shared(&dstb[dd * 132 + c * 4]);
            CP16(d, &vTb[(size_t)dd * Sx + j0 + c * 4]);
        }
    };

    // stage mask + Q
    *(float4*)&mks[4 * t] = *(const float4*)&mask[b * Sx + 4 * t];
    #pragma unroll
    for (int i = 0; i < 8; i++) {
        int id = t + i * 256;
        int rr = id >> 6, d = id & 63;
        qs[rr * 68 + d] = tf32f(base[(size_t)(q0 + rr) * TDx + h * HDx + d]);
    }

    const int ntile = (q0 + 31) / 128 + 1;
    const int Ccols = ntile * 128;

    stageK(0, 0);
    CP_COMMIT();
    __syncthreads();   // qs/mks visible

    // ---- scores ----
    for (int jt = 0; jt < ntile; jt++) {
        const int j0 = jt * 128;
        if (jt + 1 < ntile) { stageK((jt + 1) & 1, (jt + 1) * 128); CP_COMMIT(); CP_WAIT1(); }
        else                { CP_WAIT0(); }
        __syncthreads();
        const float* kvt = kvb + (jt & 1) * 8704;

        float c[4][4];
        #pragma unroll
        for (int i = 0; i < 4; i++)
            #pragma unroll
            for (int j = 0; j < 4; j++) c[i][j] = 0.f;

        #pragma unroll
        for (int ks = 0; ks < 8; ks++) {
            const int kb = ks * 8;
            unsigned a[4];
            const float* ap0 = &qs[(wm * 16 + r) * 68 + kb + cq];
            const float* ap1 = ap0 + 8 * 68;
            a[0] = __float_as_uint(ap0[0]);
            a[1] = __float_as_uint(ap1[0]);
            a[2] = __float_as_uint(ap0[4]);
            a[3] = __float_as_uint(ap1[4]);
            #pragma unroll
            for (int nn = 0; nn < 4; nn++) {
                const float* bp = &kvt[(wn * 32 + nn * 8 + r) * 68 + kb + cq];
                unsigned bf[2] = {__float_as_uint(bp[0]), __float_as_uint(bp[4])};
                mma_tf32(c[nn], a, bf);
            }
        }

        const int qa = q0 + wm * 16 + r;
        const int qb = qa + 8;
        #pragma unroll
        for (int nn = 0; nn < 4; nn++) {
            int jl = wn * 32 + nn * 8 + 2 * cq;
            int jg = j0 + jl;
            float mk0 = mks[jg], mk1 = mks[jg + 1];
            float* s0 = &sc[(wm * 16 + r) * SCS + jg];
            float* s1 = &sc[(wm * 16 + r + 8) * SCS + jg];
            s0[0] = (jg     <= qa) ? tf32f(expapx(fmaf(c[nn][0], 0.125f, mk0))) : 0.f;
            s0[1] = (jg + 1 <= qa) ? tf32f(expapx(fmaf(c[nn][1], 0.125f, mk1))) : 0.f;
            s1[0] = (jg     <= qb) ? tf32f(expapx(fmaf(c[nn][2], 0.125f, mk0))) : 0.f;
            s1[1] = (jg + 1 <= qb) ? tf32f(expapx(fmaf(c[nn][3], 0.125f, mk1))) : 0.f;
        }
        __syncthreads();
    }

    // prefetch first V tile; overlaps with rowsum + w store below
    stageV(0, 0);
    CP_COMMIT();

    // ---- rowsum + normalized w store + zero fill ----
    #pragma unroll
    for (int rr = 0; rr < 4; rr++) {
        int row = warp * 4 + rr;
        int q = q0 + row;
        float s = 0.f;
        for (int j4 = lane * 4; j4 < Ccols; j4 += 128) {
            float4 v = *(float4*)&sc[row * SCS + j4];
            s += v.x + v.y + v.z + v.w;
        }
        #pragma unroll
        for (int o = 16; o > 0; o >>= 1) s += __shfl_xor_sync(0xffffffffu, s, o);
        float inv = 1.f / s;
        if (lane == 0) invs[row] = inv;
        size_t wb = ((size_t)(bh * Sx + q)) * Sx;
        for (int j4 = lane * 4; j4 < Ccols; j4 += 128) {
            float4 v = *(float4*)&sc[row * SCS + j4];
            float4 o4 = {v.x * inv, v.y * inv, v.z * inv, v.w * inv};
            *(float4*)&w_out[wb + j4] = o4;
        }
        float4 z = {0.f, 0.f, 0.f, 0.f};
        for (int j4 = Ccols + lane * 4; j4 < Sx; j4 += 128)
            *(float4*)&w_out[wb + j4] = z;
    }
    __syncthreads();

    // ---- PV ----
    float oc[2][4];
    #pragma unroll
    for (int i = 0; i < 2; i++)
        #pragma unroll
        for (int j = 0; j < 4; j++) oc[i][j] = 0.f;

    for (int jt = 0; jt < ntile; jt++) {
        const int j0 = jt * 128;
        if (jt + 1 < ntile) { stageV((jt + 1) & 1, (jt + 1) * 128); CP_COMMIT(); CP_WAIT1(); }
        else                { CP_WAIT0(); }
        __syncthreads();
        const float* kvt = kvb + (jt & 1) * 8704;

        #pragma unroll
        for (int ks = 0; ks < 16; ks++) {
            const int kb = ks * 8;
            unsigned a[4];
            const float* ap0 = &sc[(wm * 16 + r) * SCS + j0 + kb + cq];
            const float* ap1 = ap0 + 8 * SCS;
            a[0] = __float_as_uint(ap0[0]);
            a[1] = __float_as_uint(ap1[0]);
            a[2] = __float_as_uint(ap0[4]);
            a[3] = __float_as_uint(ap1[4]);
            #pragma unroll
            for (int nn = 0; nn < 2; nn++) {
                const float* bp = &kvt[(wn * 16 + nn * 8 + r) * 132 + kb + cq];
                unsigned bf[2] = {__float_as_uint(bp[0]), __float_as_uint(bp[4])};
                mma_tf32(oc[nn], a, bf);
            }
        }
        __syncthreads();
    }

    {
        int row_a = wm * 16 + r, row_b = row_a + 8;
        float ia = invs[row_a], ib = invs[row_b];
        #pragma unroll
        for (int nn = 0; nn < 2; nn++) {
            int d = wn * 16 + nn * 8 + 2 * cq;
            size_t ra = ((size_t)(b * Sx + q0 + row_a)) * Dx + h * HDx + d;
            size_t rb = ((size_t)(b * Sx + q0 + row_b)) * Dx + h * HDx + d;
            // round to tf32 so K3 (plain tf32 GEMM) sees unbiased operands
            float2 v0 = {tf32f(oc[nn][0] * ia), tf32f(oc[nn][1] * ia)};
            float2 v1 = {tf32f(oc[nn][2] * ib), tf32f(oc[nn][3] * ib)};
            *(float2*)&aout[ra] = v0;
            *(float2*)&aout[rb] = v1;
        }
    }
}

// ---------------------------------------------------------------------------
extern "C" void kernel_launch(void* const* d_in, const int* in_sizes, int n_in,
                              void* d_out, int out_size) {
    const float* x      = (const float*)d_in[0];
    const float* mask   = (const float*)d_in[1];
    const float* w_attn = (const float*)d_in[2];
    const float* b_attn = (const float*)d_in[3];
    const float* w_proj = (const float*)d_in[4];
    const float* b_proj = (const float*)d_in[5];

    float* out_a = (float*)d_out;
    float* out_w = (float*)d_out + (size_t)Bx * Sx * Dx;

    float *qkv, *aout, *xr, *war, *wpr, *kT, *vT;
    cudaGetSymbolAddress((void**)&qkv,  g_qkv);
    cudaGetSymbolAddress((void**)&aout, g_aout);
    cudaGetSymbolAddress((void**)&xr,   g_xr);
    cudaGetSymbolAddress((void**)&war,  g_war);
    cudaGetSymbolAddress((void**)&wpr,  g_wpr);
    cudaGetSymbolAddress((void**)&kT,   g_kT);
    cudaGetSymbolAddress((void**)&vT,   g_vT);

    static const int ATTN_SMEM = 53536 * 4;   // 214144 B
    cudaFuncSetAttribute(attn_mma, cudaFuncAttributeMaxDynamicSharedMemorySize, ATTN_SMEM);

    {
        int n;
        n = Bx * Sx * Dx / 4;  round_tf32<<<(n + 255) / 256, 256>>>(x, xr, n);
        n = Dx * TDx / 4;      round_tf32<<<(n + 255) / 256, 256>>>(w_attn, war, n);
        n = Dx * Dx / 4;       round_tf32<<<(n + 255) / 256, 256>>>(w_proj, wpr, n);
    }
    {
        dim3 grid(TDx / 128, (Bx * Sx) / 128);
        gemm_mma<<<grid, 256>>>(xr, war, b_attn, qkv, Bx * Sx, TDx, Dx);
    }
    {
        prep_kT<<<(Bx * Hx * Sx * 16) / 256, 256>>>(qkv, kT);
        dim3 gv(Sx / 64, Bx * Hx);
        prep_vT<<<gv, 256>>>(qkv, vT);
    }
    {
        dim3 grid(Sx / 32, Hx, Bx);
        attn_mma<<<grid, 256, ATTN_SMEM>>>(qkv, kT, vT, mask, out_w, aout);
    }
    {
        dim3 grid(Dx / 128, (Bx * Sx) / 128);
        gemm_mma<<<grid, 256>>>(aout, wpr, b_proj, out_a, Bx * Sx, Dx, Dx);
    }
}

// round 7
// speedup vs baseline: 2.8922x; 1.0013x over previous
#include <cuda_runtime.h>
#include <cuda_bf16.h>
#include <math.h>

#define Bx 4
#define Sx 1024
#define Dx 1024
#define Hx 16
#define HDx 64
#define TDx 3072
#define SCS 1028   // scores smem row stride (== 4 mod 32 -> conflict-free frags)

__device__ float g_qkv[Bx * Sx * TDx];
__device__ float g_aout[Bx * Sx * Dx];
__device__ float g_xr[Bx * Sx * Dx];
__device__ float g_war[Dx * TDx];
__device__ float g_wpr[Dx * Dx];
__device__ float g_kT[Bx * Hx * Sx * HDx];   // [bh][j][d] tf32-rounded K
__device__ float g_vT[Bx * Hx * HDx * Sx];   // [bh][d][j] tf32-rounded V^T

// ---------------------------------------------------------------------------
__device__ __forceinline__ unsigned f2tf32(float f) {
    unsigned r;
    asm("cvt.rna.tf32.f32 %0, %1;" : "=r"(r) : "f"(f));
    return r;
}
__device__ __forceinline__ float tf32f(float f) { return __uint_as_float(f2tf32(f)); }

__device__ __forceinline__ void mma_tf32(float c[4], const unsigned a[4], const unsigned b[2]) {
    asm volatile("mma.sync.aligned.m16n8k8.row.col.f32.tf32.tf32.f32 "
        "{%0,%1,%2,%3}, {%4,%5,%6,%7}, {%8,%9}, {%0,%1,%2,%3};"
        : "+f"(c[0]), "+f"(c[1]), "+f"(c[2]), "+f"(c[3])
        : "r"(a[0]), "r"(a[1]), "r"(a[2]), "r"(a[3]), "r"(b[0]), "r"(b[1]));
}

// FFMA-only exp: exp(x) = 2^(x*log2e), deg-5 poly on [-0.5,0.5]
__device__ __forceinline__ float expapx(float x) {
    float y = fmaxf(x * 1.4426950408889634f, -80.f);
    float t = y + 12582912.f;
    int   n = __float_as_int(t) - 0x4b400000;
    float f = y - (t - 12582912.f);
    float p = 1.3333558146428443e-3f;
    p = fmaf(p, f, 9.618129842118066e-3f);
    p = fmaf(p, f, 5.550410866482158e-2f);
    p = fmaf(p, f, 2.402265069591007e-1f);
    p = fmaf(p, f, 6.931471805599453e-1f);
    p = fmaf(p, f, 1.0f);
    return __int_as_float(__float_as_int(p) + (n << 23));
}

#define CP16(dst, src) asm volatile("cp.async.cg.shared.global [%0], [%1], 16;" :: "r"(dst), "l"(src))
#define CP_COMMIT()    asm volatile("cp.async.commit_group;")
#define CP_WAIT1()     asm volatile("cp.async.wait_group 1;")
#define CP_WAIT0()     asm volatile("cp.async.wait_group 0;")

// ---------------------------------------------------------------------------
__global__ void round_tf32(const float* __restrict__ in, float* __restrict__ out, int n4) {
    int i = blockIdx.x * blockDim.x + threadIdx.x;
    if (i < n4) {
        float4 v = ((const float4*)in)[i];
        uint4 o;
        o.x = f2tf32(v.x); o.y = f2tf32(v.y); o.z = f2tf32(v.z); o.w = f2tf32(v.w);
        ((uint4*)out)[i] = o;
    }
}

// kT[bh][j][d] = tf32(K)
__global__ void prep_kT(const float* __restrict__ qkv, float* __restrict__ kT) {
    int i = blockIdx.x * 256 + threadIdx.x;
    int c = i & 15, j = (i >> 4) & 1023, bh = i >> 14;
    int b = bh >> 4, h = bh & 15;
    float4 v = *(const float4*)&qkv[((size_t)(b * Sx + j)) * TDx + Dx + h * HDx + c * 4];
    uint4 o = {f2tf32(v.x), f2tf32(v.y), f2tf32(v.z), f2tf32(v.w)};
    *(uint4*)&kT[(size_t)i * 4] = o;
}

// vT[bh][d][j] = tf32(V) — smem tile transpose
__global__ void prep_vT(const float* __restrict__ qkv, float* __restrict__ vT) {
    __shared__ float tile[64][68];
    int bh = blockIdx.y, j0 = blockIdx.x * 64;
    int b = bh >> 4, h = bh & 15;
    int t = threadIdx.x;
    #pragma unroll
    for (int i = 0; i < 4; i++) {
        int id = t + i * 256;
        int jj = id >> 4, c = id & 15;
        float4 v = *(const float4*)&qkv[((size_t)(b * Sx + j0 + jj)) * TDx + 2 * Dx + h * HDx + c * 4];
        tile[jj][c * 4 + 0] = tf32f(v.x);
        tile[jj][c * 4 + 1] = tf32f(v.y);
        tile[jj][c * 4 + 2] = tf32f(v.z);
        tile[jj][c * 4 + 3] = tf32f(v.w);
    }
    __syncthreads();
    #pragma unroll
    for (int i = 0; i < 4; i++) {
        int id = t + i * 256;
        int d = id >> 4, c = id & 15;
        float4 o = {tile[c * 4 + 0][d], tile[c * 4 + 1][d], tile[c * 4 + 2][d], tile[c * 4 + 3][d]};
        *(float4*)&vT[((size_t)(bh * HDx + d)) * Sx + j0 + c * 4] = o;
    }
}

// ---------------------------------------------------------------------------
// tf32 GEMM, 3-stage cp.async pipeline, ONE barrier per k-tile.
// Dynamic smem: As[3][128][20] + Bs[3][16][136] = 56832 B
// ---------------------------------------------------------------------------
#define GEMM_SMEM 56832
__global__ __launch_bounds__(256) void gemm_mma(const float* __restrict__ A,
                                                const float* __restrict__ B,
                                                const float* __restrict__ bias,
                                                float* __restrict__ C,
                                                int M, int N, int K) {
    extern __shared__ float gsm[];
    float* Asb = gsm;                 // 3 stages of [128][20]
    float* Bsb = gsm + 3 * 2560;      // 3 stages of [16][136]

    const int t = threadIdx.x;
    const int warp = t >> 5, lane = t & 31;
    const int wm = warp >> 2, wn = warp & 3;
    const int r = lane >> 2, cq = lane & 3;
    const int row0 = blockIdx.y * 128, col0 = blockIdx.x * 128;

    float acc[4][4][4];
    #pragma unroll
    for (int i = 0; i < 4; i++)
        #pragma unroll
        for (int j = 0; j < 4; j++)
            #pragma unroll
            for (int k = 0; k < 4; k++) acc[i][j][k] = 0.f;

    const int aM0 = (t * 2) >> 2,  aK0 = (t * 2) & 3;
    const int aM1 = (t * 2 + 1) >> 2, aK1 = (t * 2 + 1) & 3;
    const int bK0 = (t * 2) >> 5,  bN0 = (t * 2) & 31;
    const int bK1 = (t * 2 + 1) >> 5, bN1 = (t * 2 + 1) & 31;

    auto loadG = [&](int st, int k0) {
        float* As = Asb + st * 2560;
        float* Bs = Bsb + st * 2176;
        unsigned da0 = (unsigned)__cvta_generic_to_shared(&As[aM0 * 20 + aK0 * 4]);
        unsigned da1 = (unsigned)__cvta_generic_to_shared(&As[aM1 * 20 + aK1 * 4]);
        CP16(da0, &A[(size_t)(row0 + aM0) * K + k0 + aK0 * 4]);
        CP16(da1, &A[(size_t)(row0 + aM1) * K + k0 + aK1 * 4]);
        unsigned db0 = (unsigned)__cvta_generic_to_shared(&Bs[bK0 * 136 + bN0 * 4]);
        unsigned db1 = (unsigned)__cvta_generic_to_shared(&Bs[bK1 * 136 + bN1 * 4]);
        CP16(db0, &B[(size_t)(k0 + bK0) * N + col0 + bN0 * 4]);
        CP16(db1, &B[(size_t)(k0 + bK1) * N + col0 + bN1 * 4]);
    };

    loadG(0, 0);  CP_COMMIT();
    loadG(1, 16); CP_COMMIT();

    const int NT = K / 16;
    int st = 0;
    for (int kt = 0; kt < NT; kt++) {
        if (kt + 1 < NT) CP_WAIT1(); else CP_WAIT0();
        __syncthreads();
        if (kt + 2 < NT) {
            int st2 = st + 2; if (st2 >= 3) st2 -= 3;
            loadG(st2, (kt + 2) * 16);
            CP_COMMIT();
        }
        const float* As = Asb + st * 2560;
        const float* Bs = Bsb + st * 2176;

        #pragma unroll
        for (int ks = 0; ks < 2; ks++) {
            const int kb = ks * 8;
            unsigned a[4][4], b[4][2];
            #pragma unroll
            for (int mm = 0; mm < 4; mm++) {
                const float* ap0 = &As[(wm * 64 + mm * 16 + r) * 20 + kb + cq];
                const float* ap1 = ap0 + 8 * 20;
                a[mm][0] = __float_as_uint(ap0[0]);
                a[mm][1] = __float_as_uint(ap1[0]);
                a[mm][2] = __float_as_uint(ap0[4]);
                a[mm][3] = __float_as_uint(ap1[4]);
            }
            #pragma unroll
            for (int nn = 0; nn < 4; nn++) {
                const float* bp = &Bs[(kb + cq) * 136 + wn * 32 + nn * 8 + r];
                b[nn][0] = __float_as_uint(bp[0]);
                b[nn][1] = __float_as_uint(bp[4 * 136]);
            }
            #pragma unroll
            for (int mm = 0; mm < 4; mm++)
                #pragma unroll
                for (int nn = 0; nn < 4; nn++)
                    mma_tf32(acc[mm][nn], a[mm], b[nn]);
        }
        if (++st == 3) st = 0;
    }

    #pragma unroll
    for (int mm = 0; mm < 4; mm++) {
        int r0 = row0 + wm * 64 + mm * 16 + r;
        #pragma unroll
        for (int nn = 0; nn < 4; nn++) {
            int c0 = col0 + wn * 32 + nn * 8 + 2 * cq;
            float2 bv = *(const float2*)&bias[c0];
            float2 o0 = {acc[mm][nn][0] + bv.x, acc[mm][nn][1] + bv.y};
            float2 o1 = {acc[mm][nn][2] + bv.x, acc[mm][nn][3] + bv.y};
            *(float2*)&C[(size_t)r0 * N + c0] = o0;
            *(float2*)&C[(size_t)(r0 + 8) * N + c0] = o1;
        }
    }
}

// ---------------------------------------------------------------------------
// Tensor-core attention, 512 threads (16 warps) per CTA of 32 q-rows.
// Smem layout identical to R6 (214144 B).
// ---------------------------------------------------------------------------
__global__ __launch_bounds__(512) void attn_mma(const float* __restrict__ qkv,
                                                const float* __restrict__ kT,
                                                const float* __restrict__ vT,
                                                const float* __restrict__ mask,
                                                float* __restrict__ w_out,
                                                float* __restrict__ aout) {
    extern __shared__ float sm[];
    float* sc   = sm;            // [32][SCS]
    float* qs   = sm + 32896;    // [32][68]
    float* kvb  = sm + 35072;    // 2 x 8704
    float* mks  = sm + 52480;    // [1024]
    float* invs = sm + 53504;    // [32]

    const int q0 = blockIdx.x * 32;
    const int h  = blockIdx.y;
    const int b  = blockIdx.z;
    const int bh = b * Hx + h;
    const int t  = threadIdx.x;
    const int warp = t >> 5, lane = t & 31;
    const int r = lane >> 2, cq = lane & 3;
    const int wm = warp >> 3;       // 0..1 (M halves)
    const int wn = warp & 7;        // 0..7 (N groups)
    const float* base = qkv + (size_t)b * Sx * TDx;
    const float* kTb = kT + (size_t)bh * Sx * HDx;
    const float* vTb = vT + (size_t)bh * HDx * Sx;

    auto stageK = [&](int buf, int j0) {
        float* dstb = kvb + buf * 8704;
        #pragma unroll
        for (int i = 0; i < 4; i++) {
            int id = t + i * 512;
            int jj = id >> 4, c = id & 15;
            unsigned d = (unsigned)__cvta_generic_to_shared(&dstb[jj * 68 + c * 4]);
            CP16(d, &kTb[(size_t)(j0 + jj) * HDx + c * 4]);
        }
    };
    auto stageV = [&](int buf, int j0) {
        float* dstb = kvb + buf * 8704;
        #pragma unroll
        for (int i = 0; i < 4; i++) {
            int id = t + i * 512;
            int dd = id >> 5, c = id & 31;
            unsigned d = (unsigned)__cvta_generic_to_shared(&dstb[dd * 132 + c * 4]);
            CP16(d, &vTb[(size_t)dd * Sx + j0 + c * 4]);
        }
    };

    // stage mask + Q
    if (t < 256) *(float4*)&mks[4 * t] = *(const float4*)&mask[b * Sx + 4 * t];
    #pragma unroll
    for (int i = 0; i < 4; i++) {
        int id = t + i * 512;
        int rr = id >> 6, d = id & 63;
        qs[rr * 68 + d] = tf32f(base[(size_t)(q0 + rr) * TDx + h * HDx + d]);
    }

    const int ntile = (q0 + 31) / 128 + 1;
    const int Ccols = ntile * 128;

    stageK(0, 0);
    CP_COMMIT();
    __syncthreads();

    // ---- scores ----
    for (int jt = 0; jt < ntile; jt++) {
        const int j0 = jt * 128;
        if (jt + 1 < ntile) { stageK((jt + 1) & 1, (jt + 1) * 128); CP_COMMIT(); CP_WAIT1(); }
        else                { CP_WAIT0(); }
        __syncthreads();
        const float* kvt = kvb + (jt & 1) * 8704;

        float c[2][4];
        #pragma unroll
        for (int i = 0; i < 2; i++)
            #pragma unroll
            for (int j = 0; j < 4; j++) c[i][j] = 0.f;

        #pragma unroll
        for (int ks = 0; ks < 8; ks++) {
            const int kb = ks * 8;
            unsigned a[4];
            const float* ap0 = &qs[(wm * 16 + r) * 68 + kb + cq];
            const float* ap1 = ap0 + 8 * 68;
            a[0] = __float_as_uint(ap0[0]);
            a[1] = __float_as_uint(ap1[0]);
            a[2] = __float_as_uint(ap0[4]);
            a[3] = __float_as_uint(ap1[4]);
            #pragma unroll
            for (int nn = 0; nn < 2; nn++) {
                const float* bp = &kvt[(wn * 16 + nn * 8 + r) * 68 + kb + cq];
                unsigned bf[2] = {__float_as_uint(bp[0]), __float_as_uint(bp[4])};
                mma_tf32(c[nn], a, bf);
            }
        }

        const int qa = q0 + wm * 16 + r;
        const int qb = qa + 8;
        #pragma unroll
        for (int nn = 0; nn < 2; nn++) {
            int jl = wn * 16 + nn * 8 + 2 * cq;
            int jg = j0 + jl;
            float mk0 = mks[jg], mk1 = mks[jg + 1];
            float* s0 = &sc[(wm * 16 + r) * SCS + jg];
            float* s1 = &sc[(wm * 16 + r + 8) * SCS + jg];
            s0[0] = (jg     <= qa) ? tf32f(expapx(fmaf(c[nn][0], 0.125f, mk0))) : 0.f;
            s0[1] = (jg + 1 <= qa) ? tf32f(expapx(fmaf(c[nn][1], 0.125f, mk1))) : 0.f;
            s1[0] = (jg     <= qb) ? tf32f(expapx(fmaf(c[nn][2], 0.125f, mk0))) : 0.f;
            s1[1] = (jg + 1 <= qb) ? tf32f(expapx(fmaf(c[nn][3], 0.125f, mk1))) : 0.f;
        }
        __syncthreads();
    }

    // prefetch first V tile; overlaps with rowsum + w store
    stageV(0, 0);
    CP_COMMIT();

    // ---- rowsum + normalized w store + zero fill (2 rows per warp) ----
    #pragma unroll
    for (int rr = 0; rr < 2; rr++) {
        int row = warp * 2 + rr;
        int q = q0 + row;
        float s = 0.f;
        for (int j4 = lane * 4; j4 < Ccols; j4 += 128) {
            float4 v = *(float4*)&sc[row * SCS + j4];
            s += v.x + v.y + v.z + v.w;
        }
        #pragma unroll
        for (int o = 16; o > 0; o >>= 1) s += __shfl_xor_sync(0xffffffffu, s, o);
        float inv = 1.f / s;
        if (lane == 0) invs[row] = inv;
        size_t wb = ((size_t)(bh * Sx + q)) * Sx;
        for (int j4 = lane * 4; j4 < Ccols; j4 += 128) {
            float4 v = *(float4*)&sc[row * SCS + j4];
            float4 o4 = {v.x * inv, v.y * inv, v.z * inv, v.w * inv};
            *(float4*)&w_out[wb + j4] = o4;
        }
        float4 z = {0.f, 0.f, 0.f, 0.f};
        for (int j4 = Ccols + lane * 4; j4 < Sx; j4 += 128)
            *(float4*)&w_out[wb + j4] = z;
    }
    __syncthreads();

    // ---- PV: O = p @ V ----  warps: 2(M) x 8(N of 8 cols)
    float oc[4] = {0.f, 0.f, 0.f, 0.f};

    for (int jt = 0; jt < ntile; jt++) {
        const int j0 = jt * 128;
        if (jt + 1 < ntile) { stageV((jt + 1) & 1, (jt + 1) * 128); CP_COMMIT(); CP_WAIT1(); }
        else                { CP_WAIT0(); }
        __syncthreads();
        const float* kvt = kvb + (jt & 1) * 8704;

        #pragma unroll
        for (int ks = 0; ks < 16; ks++) {
            const int kb = ks * 8;
            unsigned a[4];
            const float* ap0 = &sc[(wm * 16 + r) * SCS + j0 + kb + cq];
            const float* ap1 = ap0 + 8 * SCS;
            a[0] = __float_as_uint(ap0[0]);
            a[1] = __float_as_uint(ap1[0]);
            a[2] = __float_as_uint(ap0[4]);
            a[3] = __float_as_uint(ap1[4]);
            const float* bp = &kvt[(wn * 8 + r) * 132 + kb + cq];
            unsigned bf[2] = {__float_as_uint(bp[0]), __float_as_uint(bp[4])};
            mma_tf32(oc, a, bf);
        }
        __syncthreads();
    }

    {
        int row_a = wm * 16 + r, row_b = row_a + 8;
        float ia = invs[row_a], ib = invs[row_b];
        int d = wn * 8 + 2 * cq;
        size_t ra = ((size_t)(b * Sx + q0 + row_a)) * Dx + h * HDx + d;
        size_t rb = ((size_t)(b * Sx + q0 + row_b)) * Dx + h * HDx + d;
        float2 v0 = {tf32f(oc[0] * ia), tf32f(oc[1] * ia)};
        float2 v1 = {tf32f(oc[2] * ib), tf32f(oc[3] * ib)};
        *(float2*)&aout[ra] = v0;
        *(float2*)&aout[rb] = v1;
    }
}

// ---------------------------------------------------------------------------
extern "C" void kernel_launch(void* const* d_in, const int* in_sizes, int n_in,
                              void* d_out, int out_size) {
    const float* x      = (const float*)d_in[0];
    const float* mask   = (const float*)d_in[1];
    const float* w_attn = (const float*)d_in[2];
    const float* b_attn = (const float*)d_in[3];
    const float* w_proj = (const float*)d_in[4];
    const float* b_proj = (const float*)d_in[5];

    float* out_a = (float*)d_out;
    float* out_w = (float*)d_out + (size_t)Bx * Sx * Dx;

    float *qkv, *aout, *xr, *war, *wpr, *kT, *vT;
    cudaGetSymbolAddress((void**)&qkv,  g_qkv);
    cudaGetSymbolAddress((void**)&aout, g_aout);
    cudaGetSymbolAddress((void**)&xr,   g_xr);
    cudaGetSymbolAddress((void**)&war,  g_war);
    cudaGetSymbolAddress((void**)&wpr,  g_wpr);
    cudaGetSymbolAddress((void**)&kT,   g_kT);
    cudaGetSymbolAddress((void**)&vT,   g_vT);

    static const int ATTN_SMEM = 53536 * 4;   // 214144 B
    cudaFuncSetAttribute(attn_mma, cudaFuncAttributeMaxDynamicSharedMemorySize, ATTN_SMEM);
    cudaFuncSetAttribute(gemm_mma, cudaFuncAttributeMaxDynamicSharedMemorySize, GEMM_SMEM);

    {
        int n;
        n = Bx * Sx * Dx / 4;  round_tf32<<<(n + 255) / 256, 256>>>(x, xr, n);
        n = Dx * TDx / 4;      round_tf32<<<(n + 255) / 256, 256>>>(w_attn, war, n);
        n = Dx * Dx / 4;       round_tf32<<<(n + 255) / 256, 256>>>(w_proj, wpr, n);
    }
    {
        dim3 grid(TDx / 128, (Bx * Sx) / 128);
        gemm_mma<<<grid, 256, GEMM_SMEM>>>(xr, war, b_attn, qkv, Bx * Sx, TDx, Dx);
    }
    {
        prep_kT<<<(Bx * Hx * Sx * 16) / 256, 256>>>(qkv, kT);
        dim3 gv(Sx / 64, Bx * Hx);
        prep_vT<<<gv, 256>>>(qkv, vT);
    }
    {
        dim3 grid(Sx / 32, Hx, Bx);
        attn_mma<<<grid, 512, ATTN_SMEM>>>(qkv, kT, vT, mask, out_w, aout);
    }
    {
        dim3 grid(Dx / 128, (Bx * Sx) / 128);
        gemm_mma<<<grid, 256, GEMM_SMEM>>>(aout, wpr, b_proj, out_a, Bx * Sx, Dx, Dx);
    }
}